// round 15
// baseline (speedup 1.0000x reference)
#include <cuda_runtime.h>
#include <cuda_fp16.h>
#include <math.h>
#include <stdint.h>

#define S_    1024
#define H_    1024
#define NH_   16
#define KVH_  4
#define HD_   64
#define REP_  4
#define E_    64
#define TOPK_ 8
#define ID_   1408
#define CAP_  256
#define EPS_  1e-6f
#define QKVN_ (H_ + 2 * KVH_ * HD_)   // 1536

// fp32 scratch
__device__ float g_xn1 [S_ * H_];
__device__ float g_wqkv[H_ * QKVN_];
__device__ float g_wsgsu[H_ * 2 * ID_];
__device__ float g_qkv [S_ * QKVN_];
__device__ float g_sc  [(long)NH_ * S_ * S_];
__device__ float g_hres[S_ * H_];
__device__ float g_xn2 [S_ * H_];
__device__ float g_logits[S_ * E_];
__device__ float g_coef[S_ * TOPK_];
__device__ float g_shb [S_ * H_];
__device__ int   g_topi[S_ * TOPK_];
__device__ int   g_pos [S_ * TOPK_];
__device__ int   g_cnt [E_];
// fp16 activation scratch
__device__ __half h_xn1[S_ * H_];
__device__ __half h_xn2[S_ * H_];
__device__ __half h_qr [NH_ * S_ * HD_];
__device__ __half h_kr [KVH_ * S_ * HD_];
__device__ __half h_vt [KVH_ * HD_ * S_];
__device__ __half h_sc [(long)NH_ * S_ * S_];
__device__ __half h_ao [S_ * H_];
__device__ __half h_buf[(long)E_ * CAP_ * H_];
__device__ __half h_gga[(long)E_ * CAP_ * ID_];
__device__ __half h_uua[(long)E_ * CAP_ * ID_];
__device__ __half h_gg [(long)E_ * CAP_ * ID_];
__device__ __half h_yy [(long)E_ * CAP_ * H_];
__device__ __half h_sgsu[S_ * 2 * ID_];
__device__ __half h_sg [S_ * ID_];

// ---------- helpers ----------
__device__ __forceinline__ uint32_t smem_u32(const void* p) {
    uint32_t a;
    asm("{ .reg .u64 t; cvta.to.shared.u64 t, %1; cvt.u32.u64 %0, t; }" : "=r"(a) : "l"(p));
    return a;
}
__device__ __forceinline__ uint32_t cvt2h(float lo, float hi) {
    __half2 h = __floats2half2_rn(lo, hi);
    return *reinterpret_cast<uint32_t*>(&h);
}
__device__ __forceinline__ void cp16(uint32_t dst, const void* src) {
    asm volatile("cp.async.cg.shared.global [%0], [%1], 16;" :: "r"(dst), "l"(src));
}
__device__ __forceinline__ void cp_commit() { asm volatile("cp.async.commit_group;" ::: "memory"); }
__device__ __forceinline__ void cp_wait(int n) {
    if (n <= 0)      asm volatile("cp.async.wait_group 0;" ::: "memory");
    else if (n == 1) asm volatile("cp.async.wait_group 1;" ::: "memory");
    else if (n == 2) asm volatile("cp.async.wait_group 2;" ::: "memory");
    else             asm volatile("cp.async.wait_group 3;" ::: "memory");
}
__device__ __forceinline__ void ldm_x4(uint32_t* r, uint32_t a) {
    asm volatile("ldmatrix.sync.aligned.m8n8.x4.shared.b16 {%0,%1,%2,%3}, [%4];"
        : "=r"(r[0]), "=r"(r[1]), "=r"(r[2]), "=r"(r[3]) : "r"(a));
}
__device__ __forceinline__ void ldm_x4t(uint32_t* r, uint32_t a) {
    asm volatile("ldmatrix.sync.aligned.m8n8.x4.trans.shared.b16 {%0,%1,%2,%3}, [%4];"
        : "=r"(r[0]), "=r"(r[1]), "=r"(r[2]), "=r"(r[3]) : "r"(a));
}
__device__ __forceinline__ void mma16816(float* d, const uint32_t* a, const uint32_t* b) {
    asm volatile("mma.sync.aligned.m16n8k16.row.col.f32.f16.f16.f32 "
        "{%0,%1,%2,%3}, {%4,%5,%6,%7}, {%8,%9}, {%0,%1,%2,%3};"
        : "+f"(d[0]), "+f"(d[1]), "+f"(d[2]), "+f"(d[3])
        : "r"(a[0]), "r"(a[1]), "r"(a[2]), "r"(a[3]), "r"(b[0]), "r"(b[1]));
}

// ---------- fp16 GEMM ----------
// A half (cp.async + ldmatrix).
// B weights: fp32 [K,N] gmem -> converted to half in fill (LDG+cvt+STS),
//            fragments via ldmatrix.x4.trans (mapping validated in R12).
// B activations (BHALF): half [N,K] gmem, cp.async, ldmatrix.
// C fp32 or half (CHALF; ldc/sC in halves).
template<int BN, int NST, bool BHALF, bool CHALF>
__global__ void __launch_bounds__(256, (BN == 64 && !BHALF) ? 3 : 2) hgemm_k(
    const __half* __restrict__ A, const void* __restrict__ Bv, void* __restrict__ Cv,
    int K, int lda, int ldb, int ldc, long sA, long sB, long sC, int bDiv,
    const int* __restrict__ cnt)
{
    constexpr int BM = 128, BK = 32;
    constexpr int LDA  = 40;                 // halves
    constexpr int LDBH = BN + 8;             // halves (weight tile, converted)
    constexpr int A_BY = BM * LDA * 2;       // 10240
    constexpr int B_BY = BHALF ? BN * 40 * 2 : BK * LDBH * 2;
    constexpr int STG_BY = A_BY + B_BY;
    constexpr int WGN = BN / 32, WGM = 8 / WGN;
    constexpr int WM  = BM / WGM, MT = WM / 16, NT = 4;

    const int row0 = blockIdx.y * BM;
    if (cnt != nullptr && row0 >= cnt[blockIdx.z]) return;

    extern __shared__ char sm[];
    const uint32_t smb = smem_u32(sm);
    const int tid = threadIdx.x, wid = tid >> 5, lane = tid & 31;
    const int qrw = lane >> 2, qc = lane & 3;
    A += (long)blockIdx.z * sA;
    const __half* Bh = BHALF ? (const __half*)Bv + (long)(blockIdx.z / bDiv) * sB : nullptr;
    const float*  Bf = BHALF ? nullptr : (const float*)Bv + (long)(blockIdx.z / bDiv) * sB;
    const int col0 = blockIdx.x * BN;
    const int wm0 = (wid / WGN) * WM;
    const int wn0 = (wid % WGN) * 32;
    const int nch = K / BK;
    const uint32_t aoff = ((wm0 + (lane & 15)) * LDA + ((lane >> 4) << 3)) * 2;
    const uint32_t boff = ((wn0 + ((lane >> 4) << 3) + (lane & 7)) * 40
                           + (((lane >> 3) & 1) << 3)) * 2;     // BHALF path
    const uint32_t boffw = ((lane & 15) * LDBH + ((lane >> 4) << 3)) * 2;  // weight path

    auto fill = [&](int c) {
        char* Ss = sm + (c % NST) * STG_BY;
        __half* As = (__half*)Ss;
        const int k0 = c * BK;
        const __half* Ag = A + (long)row0 * lda + k0;
        #pragma unroll
        for (int i = 0; i < 2; i++) {
            int idx = i * 256 + tid;
            int r = idx >> 2, sg = idx & 3;
            cp16(smem_u32(As + r * LDA + sg * 8), Ag + (long)r * lda + sg * 8);
        }
        if (BHALF) {
            __half* Bs = (__half*)(Ss + A_BY);
            const __half* Bg = Bh + (long)col0 * ldb + k0;
            #pragma unroll
            for (int i = 0; i < BN / 64; i++) {
                int idx = i * 256 + tid;
                int r = idx >> 2, sg = idx & 3;
                cp16(smem_u32(Bs + r * 40 + sg * 8), Bg + (long)r * ldb + sg * 8);
            }
        } else {
            // weights: LDG fp32 -> cvt -> STS half [BK][LDBH]
            __half* Bs = (__half*)(Ss + A_BY);
            const float* Bg = Bf + (long)k0 * ldb + col0;
            #pragma unroll
            for (int i = 0; i < BN / 32; i++) {          // 8*BN float4-groups / 256 thr
                int idx = i * 256 + tid;
                int r = idx / (BN / 4), cg = idx % (BN / 4);
                float4 v = *reinterpret_cast<const float4*>(Bg + (long)r * ldb + cg * 4);
                *reinterpret_cast<uint2*>(Bs + r * LDBH + cg * 4)
                    = make_uint2(cvt2h(v.x, v.y), cvt2h(v.z, v.w));
            }
        }
        cp_commit();
    };

    float acc[MT][NT][4];
    #pragma unroll
    for (int m = 0; m < MT; m++)
        #pragma unroll
        for (int n = 0; n < NT; n++)
            #pragma unroll
            for (int j = 0; j < 4; j++) acc[m][n][j] = 0.f;

    const int PF = NST - 1;
    const int F0 = (nch < PF) ? nch : PF;
    for (int c = 0; c < F0; c++) fill(c);
    int g = F0;

    for (int c = 0; c < nch; c++) {
        cp_wait(g - (c + 1));
        __syncthreads();
        if (c + PF < nch) { fill(c + PF); g++; }

        const uint32_t As_u = smb + (c % NST) * STG_BY;
        const uint32_t Bs_u = As_u + A_BY;
        #pragma unroll
        for (int ks = 0; ks < 2; ks++) {
            const int kk = ks * 16;
            uint32_t af[MT][4], bf[NT][2];
            #pragma unroll
            for (int mt = 0; mt < MT; mt++)
                ldm_x4(af[mt], As_u + aoff + (mt * 16 * LDA + kk) * 2);
            if (BHALF) {
                uint32_t t0[4], t1[4];
                ldm_x4(t0, Bs_u + boff + kk * 2);
                ldm_x4(t1, Bs_u + boff + (16 * 40 + kk) * 2);
                bf[0][0] = t0[0]; bf[0][1] = t0[1];
                bf[1][0] = t0[2]; bf[1][1] = t0[3];
                bf[2][0] = t1[0]; bf[2][1] = t1[1];
                bf[3][0] = t1[2]; bf[3][1] = t1[3];
            } else {
                #pragma unroll
                for (int ntp = 0; ntp < 2; ntp++) {
                    uint32_t t[4];
                    ldm_x4t(t, Bs_u + boffw + (kk * LDBH + wn0 + ntp * 16) * 2);
                    bf[2*ntp+0][0] = t[0]; bf[2*ntp+0][1] = t[1];
                    bf[2*ntp+1][0] = t[2]; bf[2*ntp+1][1] = t[3];
                }
            }
            #pragma unroll
            for (int mt = 0; mt < MT; mt++)
                #pragma unroll
                for (int nt = 0; nt < NT; nt++)
                    mma16816(acc[mt][nt], af[mt], bf[nt]);
        }
    }

    if (CHALF) {
        __half* Ch = (__half*)Cv + (long)blockIdx.z * sC;
        #pragma unroll
        for (int mt = 0; mt < MT; mt++) {
            const int r = row0 + wm0 + mt * 16 + qrw;
            #pragma unroll
            for (int nt = 0; nt < NT; nt++) {
                const int cc = col0 + wn0 + nt * 8 + qc * 2;
                *reinterpret_cast<uint32_t*>(Ch + (long)r * ldc + cc)
                    = cvt2h(acc[mt][nt][0], acc[mt][nt][1]);
                *reinterpret_cast<uint32_t*>(Ch + (long)(r + 8) * ldc + cc)
                    = cvt2h(acc[mt][nt][2], acc[mt][nt][3]);
            }
        }
    } else {
        float* Cf = (float*)Cv + (long)blockIdx.z * sC;
        #pragma unroll
        for (int mt = 0; mt < MT; mt++) {
            const int r = row0 + wm0 + mt * 16 + qrw;
            #pragma unroll
            for (int nt = 0; nt < NT; nt++) {
                const int cc = col0 + wn0 + nt * 8 + qc * 2;
                *reinterpret_cast<float2*>(Cf + (long)r * ldc + cc) =
                    make_float2(acc[mt][nt][0], acc[mt][nt][1]);
                *reinterpret_cast<float2*>(Cf + (long)(r + 8) * ldc + cc) =
                    make_float2(acc[mt][nt][2], acc[mt][nt][3]);
            }
        }
    }
}

// ---------- exact fp32 gemm for gate logits ----------
__global__ void sgemm64_k(const float* __restrict__ A, const float* __restrict__ B,
                          float* __restrict__ C, int M, int N, int K)
{
    const int tid = threadIdx.x;
    const int row0 = blockIdx.y * 64, col0 = blockIdx.x * 64;
    __shared__ float As[16][68];
    __shared__ float Bs[16][68];
    float acc[4][4] = {};
    const int tRow = (tid / 16) * 4, tCol = (tid % 16) * 4;
    const int aRow = tid / 4, aK = (tid % 4) * 4;
    const int bR = tid / 16, bC = (tid % 16) * 4;
    for (int k0 = 0; k0 < K; k0 += 16) {
        {
            int gr = row0 + aRow, gk = k0 + aK;
            float4 v = make_float4(0,0,0,0);
            if (gr < M && gk + 3 < K) v = *reinterpret_cast<const float4*>(A + (long)gr*K + gk);
            As[aK+0][aRow]=v.x; As[aK+1][aRow]=v.y; As[aK+2][aRow]=v.z; As[aK+3][aRow]=v.w;
        }
        {
            int gk = k0 + bR, gn = col0 + bC;
            float4 v = make_float4(0,0,0,0);
            if (gk < K && gn + 3 < N) v = *reinterpret_cast<const float4*>(B + (long)gk*N + gn);
            *reinterpret_cast<float4*>(&Bs[bR][bC]) = v;
        }
        __syncthreads();
        #pragma unroll
        for (int k = 0; k < 16; k++) {
            float rA[4], rB[4];
            #pragma unroll
            for (int m = 0; m < 4; m++) rA[m] = As[k][tRow+m];
            #pragma unroll
            for (int n = 0; n < 4; n++) rB[n] = Bs[k][tCol+n];
            #pragma unroll
            for (int m = 0; m < 4; m++)
                #pragma unroll
                for (int n = 0; n < 4; n++) acc[m][n] += rA[m]*rB[n];
        }
        __syncthreads();
    }
    #pragma unroll
    for (int m = 0; m < 4; m++) {
        int gr = row0 + tRow + m;
        if (gr >= M) continue;
        #pragma unroll
        for (int n = 0; n < 4; n++) {
            int gc = col0 + tCol + n;
            if (gc < N) C[(long)gr*N + gc] = acc[m][n];
        }
    }
}

// ---------- reductions ----------
__device__ __forceinline__ float warpSum(float v) {
    #pragma unroll
    for (int o = 16; o; o >>= 1) v += __shfl_xor_sync(0xffffffffu, v, o);
    return v;
}
__device__ __forceinline__ float warpMax(float v) {
    #pragma unroll
    for (int o = 16; o; o >>= 1) v = fmaxf(v, __shfl_xor_sync(0xffffffffu, v, o));
    return v;
}
__device__ float blockSum(float v) {
    __shared__ float sh[32]; __shared__ float tot;
    int lane = threadIdx.x & 31, wid = threadIdx.x >> 5;
    v = warpSum(v);
    if (lane == 0) sh[wid] = v;
    __syncthreads();
    int nw = (blockDim.x + 31) >> 5;
    float w = (threadIdx.x < nw) ? sh[threadIdx.x] : 0.f;
    if (wid == 0) { w = warpSum(w); if (lane == 0) tot = w; }
    __syncthreads();
    float r = tot; __syncthreads(); return r;
}
__device__ float blockMax(float v) {
    __shared__ float sh[32]; __shared__ float tot;
    int lane = threadIdx.x & 31, wid = threadIdx.x >> 5;
    v = warpMax(v);
    if (lane == 0) sh[wid] = v;
    __syncthreads();
    int nw = (blockDim.x + 31) >> 5;
    float w = (threadIdx.x < nw) ? sh[threadIdx.x] : -1e30f;
    if (wid == 0) { w = warpMax(w); if (lane == 0) tot = w; }
    __syncthreads();
    float r = tot; __syncthreads(); return r;
}

// ---------- small kernels ----------
__global__ void concat_qkv_w(const float* __restrict__ Wq, const float* __restrict__ Wk,
                             const float* __restrict__ Wv, float* __restrict__ W)
{
    int idx = blockIdx.x * blockDim.x + threadIdx.x;
    if (idx >= H_ * QKVN_) return;
    int r = idx / QKVN_, c = idx % QKVN_;
    float v;
    if (c < H_)                 v = Wq[(long)r * H_ + c];
    else if (c < H_ + KVH_*HD_) v = Wk[(long)r * (KVH_*HD_) + (c - H_)];
    else                        v = Wv[(long)r * (KVH_*HD_) + (c - H_ - KVH_*HD_)];
    W[idx] = v;
}

__global__ void concat_sgsu_w(const float* __restrict__ Wsg, const float* __restrict__ Wsu,
                              float* __restrict__ W)
{
    int idx = blockIdx.x * blockDim.x + threadIdx.x;
    if (idx >= H_ * 2 * ID_) return;
    int r = idx / (2 * ID_), c = idx % (2 * ID_);
    W[idx] = (c < ID_) ? Wsg[(long)r * ID_ + c] : Wsu[(long)r * ID_ + (c - ID_)];
}

__global__ void rmsnorm_k(const float* __restrict__ x, const float* __restrict__ w,
                          float* __restrict__ y, __half* __restrict__ yh)
{
    int t = blockIdx.x;
    const float* xr = x + (long)t * H_;
    float s = 0.f;
    for (int i = threadIdx.x; i < H_; i += blockDim.x) { float v = xr[i]; s += v * v; }
    s = blockSum(s);
    float inv = rsqrtf(s / (float)H_ + EPS_);
    for (int i = threadIdx.x; i < H_; i += blockDim.x) {
        float v = xr[i] * inv * w[i];
        if (y)  y[(long)t * H_ + i] = v;
        yh[(long)t * H_ + i] = __float2half_rn(v);
    }
}

__global__ void ropeall_k(const float* __restrict__ qkv, __half* __restrict__ hqr,
                          __half* __restrict__ hkr, __half* __restrict__ hvt)
{
    int idx = blockIdx.x * blockDim.x + threadIdx.x;
    if (idx >= 24 * S_ * HD_) return;
    int g = idx / (S_ * HD_);
    int rem = idx - g * (S_ * HD_);
    if (g < 20) {
        int d = rem % HD_, s = rem / HD_;
        int h, off; __half* dst;
        if (g < 16) { h = g;      off = 0;  dst = hqr; }
        else        { h = g - 16; off = H_; dst = hkr; }
        const float* p = qkv + (long)s * QKVN_ + off + h * HD_;
        float v  = p[d];
        float pr = (d < 32) ? -p[d + 32] : p[d - 32];
        int i = d & 31;
        float inv = expf(-(float)i * (9.210340371976184f / 32.f));
        float ang = (float)s * inv, sn, cs;
        sincosf(ang, &sn, &cs);
        dst[((long)h * S_ + s) * HD_ + d] = __float2half_rn(v * cs + pr * sn);
    } else {
        int h = g - 20;
        int s = rem % S_, d = rem / S_;
        hvt[((long)h * HD_ + d) * S_ + s] =
            __float2half_rn(qkv[(long)s * QKVN_ + H_ + KVH_*HD_ + h * HD_ + d]);
    }
}

__global__ void softmax_k(const float* __restrict__ sc, const float* __restrict__ mask,
                          __half* __restrict__ pr)
{
    int r = blockIdx.x, h = blockIdx.y;
    const float4* row = reinterpret_cast<const float4*>(sc + ((long)h * S_ + r) * S_);
    const float4* mr = reinterpret_cast<const float4*>(mask + (long)r * S_);
    int j = threadIdx.x;
    float4 v = row[j], m = mr[j];
    v.x = v.x * 0.125f + m.x;
    v.y = v.y * 0.125f + m.y;
    v.z = v.z * 0.125f + m.z;
    v.w = v.w * 0.125f + m.w;
    float mx = fmaxf(fmaxf(v.x, v.y), fmaxf(v.z, v.w));
    mx = blockMax(mx);
    v.x = expf(v.x - mx); v.y = expf(v.y - mx);
    v.z = expf(v.z - mx); v.w = expf(v.w - mx);
    float sum = v.x + v.y + v.z + v.w;
    sum = blockSum(sum);
    float inv = 1.f / sum;
    uint2 pk = make_uint2(cvt2h(v.x * inv, v.y * inv), cvt2h(v.z * inv, v.w * inv));
    reinterpret_cast<uint2*>(pr + ((long)h * S_ + r) * S_)[j] = pk;
}

__global__ void add_k(const float* __restrict__ a, const float* __restrict__ b,
                      float* __restrict__ c, long n)
{
    long i = (long)blockIdx.x * blockDim.x + threadIdx.x;
    if (i < n) c[i] = a[i] + b[i];
}

__global__ void topk_k(const float* __restrict__ logits, int* __restrict__ topi,
                       float* __restrict__ coef)
{
    int t = (blockIdx.x * blockDim.x + threadIdx.x) >> 5;
    int lane = threadIdx.x & 31;
    if (t >= S_) return;
    const float* lr = logits + (long)t * E_;
    float v0 = lr[lane], v1 = lr[lane + 32];
    unsigned long long sel = 0ull;
    float tv[TOPK_]; int ti[TOPK_];
    #pragma unroll
    for (int k = 0; k < TOPK_; k++) {
        float c0 = ((sel >> lane) & 1ull) ? -1e30f : v0;
        float c1 = ((sel >> (lane + 32)) & 1ull) ? -1e30f : v1;
        float bv; int be;
        if (c0 >= c1) { bv = c0; be = lane; } else { bv = c1; be = lane + 32; }
        #pragma unroll
        for (int o = 16; o; o >>= 1) {
            float ov = __shfl_xor_sync(0xffffffffu, bv, o);
            int   oe = __shfl_xor_sync(0xffffffffu, be, o);
            if (ov > bv || (ov == bv && oe < be)) { bv = ov; be = oe; }
        }
        sel |= 1ull << be;
        tv[k] = bv; ti[k] = be;
    }
    if (lane == 0) {
        float mx = tv[0], ex[TOPK_], sum = 0.f;
        #pragma unroll
        for (int k = 0; k < TOPK_; k++) { ex[k] = expf(tv[k] - mx); sum += ex[k]; }
        float inv = 1.f / sum;
        #pragma unroll
        for (int k = 0; k < TOPK_; k++) { topi[t*TOPK_+k] = ti[k]; coef[t*TOPK_+k] = ex[k]*inv; }
    }
}

__global__ void assign_k(const int* __restrict__ topi, int* __restrict__ pos,
                         int* __restrict__ cnt)
{
    const int e = blockIdx.x;
    __shared__ int sw[8];
    __shared__ int stot;
    int lane = threadIdx.x & 31, wid = threadIdx.x >> 5;
    int base = 0;
    for (int chunk = 0; chunk < S_ * TOPK_; chunk += 256) {
        int i = chunk + threadIdx.x;
        int p = (topi[i] == e) ? 1 : 0;
        unsigned mask = __ballot_sync(0xffffffffu, p);
        int prefix = __popc(mask & ((1u << lane) - 1u));
        if (lane == 0) sw[wid] = __popc(mask);
        __syncthreads();
        if (threadIdx.x < 8) {
            int c = sw[threadIdx.x];
            int x = c;
            #pragma unroll
            for (int o = 1; o < 8; o <<= 1) {
                int y = __shfl_up_sync(0xffu, x, o);
                if ((int)threadIdx.x >= o) x += y;
            }
            sw[threadIdx.x] = x - c;
            if (threadIdx.x == 7) stot = x;
        }
        __syncthreads();
        if (p) pos[i] = base + sw[wid] + prefix;
        base += stot;
        __syncthreads();
    }
    if (threadIdx.x == 0) cnt[e] = (base < CAP_) ? base : CAP_;
}

__global__ void scatter_k(const __half* __restrict__ hxn2, const int* __restrict__ topi,
                          const int* __restrict__ pos, __half* __restrict__ buf)
{
    int i = blockIdx.x;
    int p = pos[i];
    if (p >= CAP_) return;
    int e = topi[i];
    int t = i >> 3;
    const uint2* src = reinterpret_cast<const uint2*>(hxn2 + (long)t * H_);
    uint2* dst = reinterpret_cast<uint2*>(buf + ((long)e * CAP_ + p) * H_);
    dst[threadIdx.x] = src[threadIdx.x];
}

__global__ void act_expert_k(const __half* __restrict__ ga, const __half* __restrict__ ua,
                             __half* __restrict__ o, const int* __restrict__ cnt)
{
    int e = blockIdx.x >> 8, c = blockIdx.x & 255;
    if (c >= cnt[e]) return;
    long base = ((long)e * CAP_ + c) * ID_;
    const __half2* g2 = reinterpret_cast<const __half2*>(ga + base);
    const __half2* u2 = reinterpret_cast<const __half2*>(ua + base);
    __half2* o2 = reinterpret_cast<__half2*>(o + base);
    for (int j = threadIdx.x; j < ID_ / 2; j += blockDim.x) {
        float2 g = __half22float2(g2[j]);
        float2 u = __half22float2(u2[j]);
        float a = (g.x / (1.f + expf(-g.x))) * u.x;
        float b = (g.y / (1.f + expf(-g.y))) * u.y;
        o2[j] = __floats2half2_rn(a, b);
    }
}

__global__ void act_fused_k(const __half* __restrict__ in, __half* __restrict__ o)
{
    long i = (long)blockIdx.x * blockDim.x + threadIdx.x;
    if (i >= (long)S_ * (ID_ / 2)) return;
    int row = (int)(i / (ID_ / 2)), col = (int)(i % (ID_ / 2));
    const __half2* g2 = reinterpret_cast<const __half2*>(in + (long)row * 2 * ID_) + col;
    const __half2* u2 = reinterpret_cast<const __half2*>(in + (long)row * 2 * ID_ + ID_) + col;
    float2 g = __half22float2(*g2);
    float2 u = __half22float2(*u2);
    float a = (g.x / (1.f + expf(-g.x))) * u.x;
    float b = (g.y / (1.f + expf(-g.y))) * u.y;
    reinterpret_cast<__half2*>(o + (long)row * ID_)[col] = __floats2half2_rn(a, b);
}

__global__ void final_k(const float* __restrict__ hres, const float* __restrict__ shb,
                        const __half* __restrict__ yy, const int* __restrict__ topi,
                        const int* __restrict__ pos, const float* __restrict__ coef,
                        float* __restrict__ out)
{
    int t = blockIdx.x, j = threadIdx.x;
    float4 a = reinterpret_cast<const float4*>(hres)[(long)t*256 + j];
    float4 b = reinterpret_cast<const float4*>(shb)[(long)t*256 + j];
    a.x += b.x; a.y += b.y; a.z += b.z; a.w += b.w;
    #pragma unroll
    for (int k = 0; k < TOPK_; k++) {
        int idx = t * TOPK_ + k;
        int p = pos[idx];
        if (p < CAP_) {
            float c = coef[idx];
            uint2 pk = reinterpret_cast<const uint2*>(yy + ((long)topi[idx]*CAP_ + p)*H_)[j];
            float2 f0 = __half22float2(*reinterpret_cast<__half2*>(&pk.x));
            float2 f1 = __half22float2(*reinterpret_cast<__half2*>(&pk.y));
            a.x += c*f0.x; a.y += c*f0.y; a.z += c*f1.x; a.w += c*f1.y;
        }
    }
    reinterpret_cast<float4*>(out)[(long)t*256 + j] = a;
}

// ---------- host-side smem size ----------
static int smemB(int BN, int NST, bool bhalf) {
    int A_BY = 128 * 40 * 2;
    int B_BY = bhalf ? BN * 40 * 2 : 32 * (BN + 8) * 2;
    return NST * (A_BY + B_BY);
}

extern "C" void kernel_launch(void* const* d_in, const int* in_sizes, int n_in,
                              void* d_out, int out_size)
{
    (void)in_sizes; (void)n_in; (void)out_size;
    cudaStream_t st = 0;

    const int SM_W128 = smemB(128, 4, false);   // 75,776
    const int SM_W64  = smemB(64,  4, false);   // 59,392
    const int SM_SCR  = smemB(128, 2, true);
    const int SM_PV   = smemB(64,  4, true);
    cudaFuncSetAttribute(hgemm_k<128, 4, false, true >, cudaFuncAttributeMaxDynamicSharedMemorySize, SM_W128);
    cudaFuncSetAttribute(hgemm_k<64,  4, false, false>, cudaFuncAttributeMaxDynamicSharedMemorySize, SM_W64);
    cudaFuncSetAttribute(hgemm_k<64,  4, false, true >, cudaFuncAttributeMaxDynamicSharedMemorySize, SM_W64);
    cudaFuncSetAttribute(hgemm_k<128, 2, true,  false>, cudaFuncAttributeMaxDynamicSharedMemorySize, SM_SCR);
    cudaFuncSetAttribute(hgemm_k<64,  4, true,  true >, cudaFuncAttributeMaxDynamicSharedMemorySize, SM_PV);

    const float* x     = (const float*)d_in[0];
    const float* mask  = (const float*)d_in[1];
    const float* wln1  = (const float*)d_in[2];
    const float* wln2  = (const float*)d_in[3];
    const float* Wq    = (const float*)d_in[4];
    const float* Wk    = (const float*)d_in[5];
    const float* Wv    = (const float*)d_in[6];
    const float* Wo    = (const float*)d_in[7];
    const float* Wgate = (const float*)d_in[8];
    const float* Weg   = (const float*)d_in[9];
    const float* Weu   = (const float*)d_in[10];
    const float* Wed   = (const float*)d_in[11];
    const float* Wsg   = (const float*)d_in[12];
    const float* Wsu   = (const float*)d_in[13];
    const float* Wsd   = (const float*)d_in[14];
    float* out = (float*)d_out;

    void *p;
    #define GETF(sym, var) cudaGetSymbolAddress(&p, sym); float* var = (float*)p;
    #define GETH(sym, var) cudaGetSymbolAddress(&p, sym); __half* var = (__half*)p;
    #define GETI(sym, var) cudaGetSymbolAddress(&p, sym); int* var = (int*)p;
    GETF(g_xn1, xn1)  GETF(g_wqkv, wqkv) GETF(g_wsgsu, wsgsu) GETF(g_qkv, qkv)
    GETF(g_sc, sc)    GETF(g_hres, hres) GETF(g_xn2, xn2)  GETF(g_logits, logits)
    GETF(g_coef, coef) GETF(g_shb, shb)
    GETH(h_xn1, hxn1) GETH(h_xn2, hxn2)  GETH(h_qr, hqr)   GETH(h_kr, hkr)
    GETH(h_vt, hvt)   GETH(h_sc, hsc)    GETH(h_ao, hao)   GETH(h_buf, hbuf)
    GETH(h_gga, hgga) GETH(h_uua, huua)  GETH(h_gg, hgg)   GETH(h_yy, hyy)
    GETH(h_sgsu, hsgsu) GETH(h_sg, hsg)
    GETI(g_topi, topi) GETI(g_pos, pos)  GETI(g_cnt, cnt)
    #undef GETF
    #undef GETH
    #undef GETI

    auto gw64 = [&](const __half* A, const float* B, float* C, int M, int N, int K,
                    int lda, int ldb, int ldc) {
        dim3 grid(N / 64, M / 128, 1);
        hgemm_k<64, 4, false, false><<<grid, 256, SM_W64, st>>>(
            A, B, C, K, lda, ldb, ldc, 0, 0, 0, 1, nullptr);
    };
    auto gw64h = [&](const __half* A, const float* B, __half* C, int M, int N, int K,
                     int lda, int ldb, int ldc) {
        dim3 grid(N / 64, M / 128, 1);
        hgemm_k<64, 4, false, true><<<grid, 256, SM_W64, st>>>(
            A, B, C, K, lda, ldb, ldc, 0, 0, 0, 1, nullptr);
    };
    auto gwh = [&](const __half* A, const float* B, __half* C, int M, int N, int K,
                   int lda, int ldb, int ldc, long sA, long sB, long sC, int batch,
                   const int* cc) {
        dim3 grid(N / 128, M / 128, batch);
        hgemm_k<128, 4, false, true><<<grid, 256, SM_W128, st>>>(
            A, B, C, K, lda, ldb, ldc, sA, sB, sC, 1, cc);
    };

    // ===== attention =====
    rmsnorm_k<<<S_, 256, 0, st>>>(x, wln1, nullptr, hxn1);                          // idx 0
    concat_qkv_w<<<(H_ * QKVN_ + 255)/256, 256, 0, st>>>(Wq, Wk, Wv, wqkv);         // idx 1
    concat_sgsu_w<<<(H_ * 2 * ID_ + 255)/256, 256, 0, st>>>(Wsg, Wsu, wsgsu);       // idx 2
    gw64(hxn1, wqkv, qkv, S_, QKVN_, H_, H_, QKVN_, QKVN_);                         // idx 3 (ncu)

    ropeall_k<<<(24*S_*HD_ + 255)/256, 256, 0, st>>>(qkv, hqr, hkr, hvt);

    {
        dim3 grid(S_/128, S_/128, NH_);
        hgemm_k<128, 2, true, false><<<grid, 256, SM_SCR, st>>>(
            hqr, hkr, sc, HD_, HD_, HD_, S_,
            (long)S_*HD_, (long)S_*HD_, (long)S_*S_, REP_, nullptr);
    }

    softmax_k<<<dim3(S_, NH_), 256, 0, st>>>(sc, mask, hsc);

    {
        dim3 grid(1, S_/128, NH_);
        hgemm_k<64, 4, true, true><<<grid, 256, SM_PV, st>>>(
            hsc, hvt, hao, S_, S_, S_, H_,
            (long)S_*S_, (long)HD_*S_, 64L, REP_, nullptr);
    }

    gw64(hao, Wo, xn1, S_, H_, H_, H_, H_, H_);
    add_k<<<(S_*H_ + 255)/256, 256, 0, st>>>(x, xn1, hres, (long)S_*H_);

    // ===== MoE =====
    rmsnorm_k<<<S_, 256, 0, st>>>(hres, wln2, xn2, hxn2);

    sgemm64_k<<<dim3(1, S_/64), 256, 0, st>>>(xn2, Wgate, logits, S_, E_, H_);
    topk_k<<<(S_*32 + 255)/256, 256, 0, st>>>(logits, topi, coef);
    assign_k<<<E_, 256, 0, st>>>(topi, pos, cnt);

    scatter_k<<<S_*TOPK_, 256, 0, st>>>(hxn2, topi, pos, hbuf);

    gwh(hbuf, Weg, hgga, CAP_, ID_, H_, H_, ID_, ID_,
        (long)CAP_*H_, (long)H_*ID_, (long)CAP_*ID_, E_, cnt);
    gwh(hbuf, Weu, huua, CAP_, ID_, H_, H_, ID_, ID_,
        (long)CAP_*H_, (long)H_*ID_, (long)CAP_*ID_, E_, cnt);

    act_expert_k<<<E_ * CAP_, 256, 0, st>>>(hgga, huua, hgg, cnt);

    gwh(hgg, Wed, hyy, CAP_, H_, ID_, ID_, H_, H_,
        (long)CAP_*ID_, (long)ID_*H_, (long)CAP_*H_, E_, cnt);

    // shared expert: fused gate|up GEMM then fused activation
    gw64h(hxn2, wsgsu, hsgsu, S_, 2*ID_, H_, H_, 2*ID_, 2*ID_);
    act_fused_k<<<(int)(((long)S_*(ID_/2) + 255)/256), 256, 0, st>>>(hsgsu, hsg);
    gw64(hsg, Wsd, shb, S_, H_, ID_, ID_, H_, H_);

    final_k<<<S_, 256, 0, st>>>(hres, shb, hyy, topi, pos, coef, out);
}

// round 16
// speedup vs baseline: 1.0447x; 1.0447x over previous
#include <cuda_runtime.h>
#include <cuda_fp16.h>
#include <math.h>
#include <stdint.h>

#define S_    1024
#define H_    1024
#define NH_   16
#define KVH_  4
#define HD_   64
#define REP_  4
#define E_    64
#define TOPK_ 8
#define ID_   1408
#define CAP_  256
#define EPS_  1e-6f
#define QKVN_ (H_ + 2 * KVH_ * HD_)   // 1536

// fp32 scratch
__device__ float g_xn1 [S_ * H_];
__device__ float g_wqkv[H_ * QKVN_];
__device__ float g_wsgsu[H_ * 2 * ID_];
__device__ float g_hres[S_ * H_];
__device__ float g_xn2 [S_ * H_];
__device__ float g_logits[S_ * E_];
__device__ float g_coef[S_ * TOPK_];
__device__ float g_shb [S_ * H_];
__device__ int   g_topi[S_ * TOPK_];
__device__ int   g_pos [S_ * TOPK_];
__device__ int   g_cnt [E_];
// fp16 activation scratch
__device__ __half h_xn1[S_ * H_];
__device__ __half h_xn2[S_ * H_];
__device__ __half h_qkv[S_ * QKVN_];
__device__ __half h_qr [NH_ * S_ * HD_];
__device__ __half h_kr [KVH_ * S_ * HD_];
__device__ __half h_vt [KVH_ * HD_ * S_];
__device__ __half h_scraw[(long)NH_ * S_ * S_];
__device__ __half h_sc [(long)NH_ * S_ * S_];
__device__ __half h_ao [S_ * H_];
__device__ __half h_buf[(long)E_ * CAP_ * H_];
__device__ __half h_gga[(long)E_ * CAP_ * ID_];
__device__ __half h_uua[(long)E_ * CAP_ * ID_];
__device__ __half h_gg [(long)E_ * CAP_ * ID_];
__device__ __half h_yy [(long)E_ * CAP_ * H_];
__device__ __half h_sgsu[S_ * 2 * ID_];
__device__ __half h_sg [S_ * ID_];

// ---------- helpers ----------
__device__ __forceinline__ uint32_t smem_u32(const void* p) {
    uint32_t a;
    asm("{ .reg .u64 t; cvta.to.shared.u64 t, %1; cvt.u32.u64 %0, t; }" : "=r"(a) : "l"(p));
    return a;
}
__device__ __forceinline__ uint32_t cvt2h(float lo, float hi) {
    __half2 h = __floats2half2_rn(lo, hi);
    return *reinterpret_cast<uint32_t*>(&h);
}
__device__ __forceinline__ void cp16(uint32_t dst, const void* src) {
    asm volatile("cp.async.cg.shared.global [%0], [%1], 16;" :: "r"(dst), "l"(src));
}
__device__ __forceinline__ void cp_commit() { asm volatile("cp.async.commit_group;" ::: "memory"); }
__device__ __forceinline__ void cp_wait(int n) {
    if (n <= 0)      asm volatile("cp.async.wait_group 0;" ::: "memory");
    else if (n == 1) asm volatile("cp.async.wait_group 1;" ::: "memory");
    else if (n == 2) asm volatile("cp.async.wait_group 2;" ::: "memory");
    else             asm volatile("cp.async.wait_group 3;" ::: "memory");
}
__device__ __forceinline__ void ldm_x4(uint32_t* r, uint32_t a) {
    asm volatile("ldmatrix.sync.aligned.m8n8.x4.shared.b16 {%0,%1,%2,%3}, [%4];"
        : "=r"(r[0]), "=r"(r[1]), "=r"(r[2]), "=r"(r[3]) : "r"(a));
}
__device__ __forceinline__ void mma16816(float* d, const uint32_t* a, const uint32_t* b) {
    asm volatile("mma.sync.aligned.m16n8k16.row.col.f32.f16.f16.f32 "
        "{%0,%1,%2,%3}, {%4,%5,%6,%7}, {%8,%9}, {%0,%1,%2,%3};"
        : "+f"(d[0]), "+f"(d[1]), "+f"(d[2]), "+f"(d[3])
        : "r"(a[0]), "r"(a[1]), "r"(a[2]), "r"(a[3]), "r"(b[0]), "r"(b[1]));
}

// ---------- fp16 GEMM (R13 proven mainloop) ----------
// A half (cp.async + ldmatrix); B fp32 [K,N] (weights, cp.async + cvt in-reg)
// or half [N,K] (cp.async + ldmatrix). C fp32 or half (CHALF; ldc/sC in halves).
template<int BN, int NST, bool BHALF, bool CHALF>
__global__ void __launch_bounds__(256, 2) hgemm_k(
    const __half* __restrict__ A, const void* __restrict__ Bv, void* __restrict__ Cv,
    int K, int lda, int ldb, int ldc, long sA, long sB, long sC, int bDiv,
    const int* __restrict__ cnt)
{
    constexpr int BM = 128, BK = 32;
    constexpr int LDA  = 40;
    constexpr int LDBF = BN + 4;
    constexpr int A_BY = BM * LDA * 2;
    constexpr int B_BY = BHALF ? BN * 40 * 2 : BK * LDBF * 4;
    constexpr int STG_BY = A_BY + B_BY;
    constexpr int WGN = BN / 32, WGM = 8 / WGN;
    constexpr int WM  = BM / WGM, MT = WM / 16, NT = 4;

    const int row0 = blockIdx.y * BM;
    if (cnt != nullptr && row0 >= cnt[blockIdx.z]) return;

    extern __shared__ char sm[];
    const uint32_t smb = smem_u32(sm);
    const int tid = threadIdx.x, wid = tid >> 5, lane = tid & 31;
    const int qrw = lane >> 2, qc = lane & 3;
    A += (long)blockIdx.z * sA;
    const __half* Bh = BHALF ? (const __half*)Bv + (long)(blockIdx.z / bDiv) * sB : nullptr;
    const float*  Bf = BHALF ? nullptr : (const float*)Bv + (long)(blockIdx.z / bDiv) * sB;
    const int col0 = blockIdx.x * BN;
    const int wm0 = (wid / WGN) * WM;
    const int wn0 = (wid % WGN) * 32;
    const int nch = K / BK;
    const uint32_t aoff = ((wm0 + (lane & 15)) * LDA + ((lane >> 4) << 3)) * 2;
    const uint32_t boff = ((wn0 + ((lane >> 4) << 3) + (lane & 7)) * 40
                           + (((lane >> 3) & 1) << 3)) * 2;

    auto fill = [&](int c) {
        char* Ss = sm + (c % NST) * STG_BY;
        __half* As = (__half*)Ss;
        const int k0 = c * BK;
        const __half* Ag = A + (long)row0 * lda + k0;
        #pragma unroll
        for (int i = 0; i < 2; i++) {
            int idx = i * 256 + tid;
            int r = idx >> 2, sg = idx & 3;
            cp16(smem_u32(As + r * LDA + sg * 8), Ag + (long)r * lda + sg * 8);
        }
        if (BHALF) {
            __half* Bs = (__half*)(Ss + A_BY);
            const __half* Bg = Bh + (long)col0 * ldb + k0;
            #pragma unroll
            for (int i = 0; i < BN / 64; i++) {
                int idx = i * 256 + tid;
                int r = idx >> 2, sg = idx & 3;
                cp16(smem_u32(Bs + r * 40 + sg * 8), Bg + (long)r * ldb + sg * 8);
            }
        } else {
            float* Bs = (float*)(Ss + A_BY);
            const float* Bg = Bf + (long)k0 * ldb + col0;
            #pragma unroll
            for (int i = 0; i < BN / 32; i++) {
                int idx = i * 256 + tid;
                int r = idx / (BN / 4), sg = idx % (BN / 4);
                cp16(smem_u32(Bs + r * LDBF + sg * 4), Bg + (long)r * ldb + sg * 4);
            }
        }
        cp_commit();
    };

    float acc[MT][NT][4];
    #pragma unroll
    for (int m = 0; m < MT; m++)
        #pragma unroll
        for (int n = 0; n < NT; n++)
            #pragma unroll
            for (int j = 0; j < 4; j++) acc[m][n][j] = 0.f;

    const int PF = NST - 1;
    const int F0 = (nch < PF) ? nch : PF;
    for (int c = 0; c < F0; c++) fill(c);
    int g = F0;

    for (int c = 0; c < nch; c++) {
        cp_wait(g - (c + 1));
        __syncthreads();
        if (c + PF < nch) { fill(c + PF); g++; }

        const uint32_t As_u = smb + (c % NST) * STG_BY;
        const uint32_t Bs_u = As_u + A_BY;
        #pragma unroll
        for (int ks = 0; ks < 2; ks++) {
            const int kk = ks * 16;
            uint32_t af[MT][4], bf[NT][2];
            #pragma unroll
            for (int mt = 0; mt < MT; mt++)
                ldm_x4(af[mt], As_u + aoff + (mt * 16 * LDA + kk) * 2);
            if (BHALF) {
                uint32_t t0[4], t1[4];
                ldm_x4(t0, Bs_u + boff + kk * 2);
                ldm_x4(t1, Bs_u + boff + (16 * 40 + kk) * 2);
                bf[0][0] = t0[0]; bf[0][1] = t0[1];
                bf[1][0] = t0[2]; bf[1][1] = t0[3];
                bf[2][0] = t1[0]; bf[2][1] = t1[1];
                bf[3][0] = t1[2]; bf[3][1] = t1[3];
            } else {
                const float* Bsf = (const float*)(sm + (c % NST) * STG_BY + A_BY);
                #pragma unroll
                for (int nt = 0; nt < NT; nt++) {
                    const float* bp = Bsf + (kk + 2 * qc) * LDBF + wn0 + nt * 8 + qrw;
                    bf[nt][0] = cvt2h(bp[0], bp[LDBF]);
                    bf[nt][1] = cvt2h(bp[8 * LDBF], bp[9 * LDBF]);
                }
            }
            #pragma unroll
            for (int mt = 0; mt < MT; mt++)
                #pragma unroll
                for (int nt = 0; nt < NT; nt++)
                    mma16816(acc[mt][nt], af[mt], bf[nt]);
        }
    }

    if (CHALF) {
        __half* Ch = (__half*)Cv + (long)blockIdx.z * sC;
        #pragma unroll
        for (int mt = 0; mt < MT; mt++) {
            const int r = row0 + wm0 + mt * 16 + qrw;
            #pragma unroll
            for (int nt = 0; nt < NT; nt++) {
                const int cc = col0 + wn0 + nt * 8 + qc * 2;
                *reinterpret_cast<uint32_t*>(Ch + (long)r * ldc + cc)
                    = cvt2h(acc[mt][nt][0], acc[mt][nt][1]);
                *reinterpret_cast<uint32_t*>(Ch + (long)(r + 8) * ldc + cc)
                    = cvt2h(acc[mt][nt][2], acc[mt][nt][3]);
            }
        }
    } else {
        float* Cf = (float*)Cv + (long)blockIdx.z * sC;
        #pragma unroll
        for (int mt = 0; mt < MT; mt++) {
            const int r = row0 + wm0 + mt * 16 + qrw;
            #pragma unroll
            for (int nt = 0; nt < NT; nt++) {
                const int cc = col0 + wn0 + nt * 8 + qc * 2;
                *reinterpret_cast<float2*>(Cf + (long)r * ldc + cc) =
                    make_float2(acc[mt][nt][0], acc[mt][nt][1]);
                *reinterpret_cast<float2*>(Cf + (long)(r + 8) * ldc + cc) =
                    make_float2(acc[mt][nt][2], acc[mt][nt][3]);
            }
        }
    }
}

// ---------- exact fp32 gemm for gate logits ----------
__global__ void sgemm64_k(const float* __restrict__ A, const float* __restrict__ B,
                          float* __restrict__ C, int M, int N, int K)
{
    const int tid = threadIdx.x;
    const int row0 = blockIdx.y * 64, col0 = blockIdx.x * 64;
    __shared__ float As[16][68];
    __shared__ float Bs[16][68];
    float acc[4][4] = {};
    const int tRow = (tid / 16) * 4, tCol = (tid % 16) * 4;
    const int aRow = tid / 4, aK = (tid % 4) * 4;
    const int bR = tid / 16, bC = (tid % 16) * 4;
    for (int k0 = 0; k0 < K; k0 += 16) {
        {
            int gr = row0 + aRow, gk = k0 + aK;
            float4 v = make_float4(0,0,0,0);
            if (gr < M && gk + 3 < K) v = *reinterpret_cast<const float4*>(A + (long)gr*K + gk);
            As[aK+0][aRow]=v.x; As[aK+1][aRow]=v.y; As[aK+2][aRow]=v.z; As[aK+3][aRow]=v.w;
        }
        {
            int gk = k0 + bR, gn = col0 + bC;
            float4 v = make_float4(0,0,0,0);
            if (gk < K && gn + 3 < N) v = *reinterpret_cast<const float4*>(B + (long)gk*N + gn);
            *reinterpret_cast<float4*>(&Bs[bR][bC]) = v;
        }
        __syncthreads();
        #pragma unroll
        for (int k = 0; k < 16; k++) {
            float rA[4], rB[4];
            #pragma unroll
            for (int m = 0; m < 4; m++) rA[m] = As[k][tRow+m];
            #pragma unroll
            for (int n = 0; n < 4; n++) rB[n] = Bs[k][tCol+n];
            #pragma unroll
            for (int m = 0; m < 4; m++)
                #pragma unroll
                for (int n = 0; n < 4; n++) acc[m][n] += rA[m]*rB[n];
        }
        __syncthreads();
    }
    #pragma unroll
    for (int m = 0; m < 4; m++) {
        int gr = row0 + tRow + m;
        if (gr >= M) continue;
        #pragma unroll
        for (int n = 0; n < 4; n++) {
            int gc = col0 + tCol + n;
            if (gc < N) C[(long)gr*N + gc] = acc[m][n];
        }
    }
}

// ---------- reductions ----------
__device__ __forceinline__ float warpSum(float v) {
    #pragma unroll
    for (int o = 16; o; o >>= 1) v += __shfl_xor_sync(0xffffffffu, v, o);
    return v;
}
__device__ __forceinline__ float warpMax(float v) {
    #pragma unroll
    for (int o = 16; o; o >>= 1) v = fmaxf(v, __shfl_xor_sync(0xffffffffu, v, o));
    return v;
}
__device__ float blockSum(float v) {
    __shared__ float sh[32]; __shared__ float tot;
    int lane = threadIdx.x & 31, wid = threadIdx.x >> 5;
    v = warpSum(v);
    if (lane == 0) sh[wid] = v;
    __syncthreads();
    int nw = (blockDim.x + 31) >> 5;
    float w = (threadIdx.x < nw) ? sh[threadIdx.x] : 0.f;
    if (wid == 0) { w = warpSum(w); if (lane == 0) tot = w; }
    __syncthreads();
    float r = tot; __syncthreads(); return r;
}
__device__ float blockMax(float v) {
    __shared__ float sh[32]; __shared__ float tot;
    int lane = threadIdx.x & 31, wid = threadIdx.x >> 5;
    v = warpMax(v);
    if (lane == 0) sh[wid] = v;
    __syncthreads();
    int nw = (blockDim.x + 31) >> 5;
    float w = (threadIdx.x < nw) ? sh[threadIdx.x] : -1e30f;
    if (wid == 0) { w = warpMax(w); if (lane == 0) tot = w; }
    __syncthreads();
    float r = tot; __syncthreads(); return r;
}

// ---------- small kernels ----------
__global__ void concat_qkv_w(const float* __restrict__ Wq, const float* __restrict__ Wk,
                             const float* __restrict__ Wv, float* __restrict__ W)
{
    int idx = blockIdx.x * blockDim.x + threadIdx.x;
    if (idx >= H_ * QKVN_) return;
    int r = idx / QKVN_, c = idx % QKVN_;
    float v;
    if (c < H_)                 v = Wq[(long)r * H_ + c];
    else if (c < H_ + KVH_*HD_) v = Wk[(long)r * (KVH_*HD_) + (c - H_)];
    else                        v = Wv[(long)r * (KVH_*HD_) + (c - H_ - KVH_*HD_)];
    W[idx] = v;
}

__global__ void concat_sgsu_w(const float* __restrict__ Wsg, const float* __restrict__ Wsu,
                              float* __restrict__ W)
{
    int idx = blockIdx.x * blockDim.x + threadIdx.x;
    if (idx >= H_ * 2 * ID_) return;
    int r = idx / (2 * ID_), c = idx % (2 * ID_);
    W[idx] = (c < ID_) ? Wsg[(long)r * ID_ + c] : Wsu[(long)r * ID_ + (c - ID_)];
}

__global__ void rmsnorm_k(const float* __restrict__ x, const float* __restrict__ w,
                          float* __restrict__ y, __half* __restrict__ yh)
{
    int t = blockIdx.x;
    const float* xr = x + (long)t * H_;
    float s = 0.f;
    for (int i = threadIdx.x; i < H_; i += blockDim.x) { float v = xr[i]; s += v * v; }
    s = blockSum(s);
    float inv = rsqrtf(s / (float)H_ + EPS_);
    for (int i = threadIdx.x; i < H_; i += blockDim.x) {
        float v = xr[i] * inv * w[i];
        if (y)  y[(long)t * H_ + i] = v;
        yh[(long)t * H_ + i] = __float2half_rn(v);
    }
}

// fused rope(q)+rope(k)+V-transpose, reading half qkv
__global__ void ropeall_k(const __half* __restrict__ qkv, __half* __restrict__ hqr,
                          __half* __restrict__ hkr, __half* __restrict__ hvt)
{
    int idx = blockIdx.x * blockDim.x + threadIdx.x;
    if (idx >= 24 * S_ * HD_) return;
    int g = idx / (S_ * HD_);
    int rem = idx - g * (S_ * HD_);
    if (g < 20) {
        int d = rem % HD_, s = rem / HD_;
        int h, off; __half* dst;
        if (g < 16) { h = g;      off = 0;  dst = hqr; }
        else        { h = g - 16; off = H_; dst = hkr; }
        const __half* p = qkv + (long)s * QKVN_ + off + h * HD_;
        float v  = __half2float(p[d]);
        float pr = (d < 32) ? -__half2float(p[d + 32]) : __half2float(p[d - 32]);
        int i = d & 31;
        float inv = expf(-(float)i * (9.210340371976184f / 32.f));
        float ang = (float)s * inv, sn, cs;
        sincosf(ang, &sn, &cs);
        dst[((long)h * S_ + s) * HD_ + d] = __float2half_rn(v * cs + pr * sn);
    } else {
        int h = g - 20;
        int s = rem % S_, d = rem / S_;
        hvt[((long)h * HD_ + d) * S_ + s] =
            qkv[(long)s * QKVN_ + H_ + KVH_*HD_ + h * HD_ + d];
    }
}

// masked softmax: half scores in, half probs out (mask fp32)
__global__ void softmax_k(const __half* __restrict__ sc, const float* __restrict__ mask,
                          __half* __restrict__ pr)
{
    int r = blockIdx.x, h = blockIdx.y;
    const uint2* row = reinterpret_cast<const uint2*>(sc + ((long)h * S_ + r) * S_);
    const float4* mr = reinterpret_cast<const float4*>(mask + (long)r * S_);
    int j = threadIdx.x;
    uint2 pk = row[j];
    float2 s0 = __half22float2(*reinterpret_cast<__half2*>(&pk.x));
    float2 s1 = __half22float2(*reinterpret_cast<__half2*>(&pk.y));
    float4 m = mr[j];
    float4 v;
    v.x = s0.x * 0.125f + m.x;
    v.y = s0.y * 0.125f + m.y;
    v.z = s1.x * 0.125f + m.z;
    v.w = s1.y * 0.125f + m.w;
    float mx = fmaxf(fmaxf(v.x, v.y), fmaxf(v.z, v.w));
    mx = blockMax(mx);
    v.x = expf(v.x - mx); v.y = expf(v.y - mx);
    v.z = expf(v.z - mx); v.w = expf(v.w - mx);
    float sum = v.x + v.y + v.z + v.w;
    sum = blockSum(sum);
    float inv = 1.f / sum;
    uint2 po = make_uint2(cvt2h(v.x * inv, v.y * inv), cvt2h(v.z * inv, v.w * inv));
    reinterpret_cast<uint2*>(pr + ((long)h * S_ + r) * S_)[j] = po;
}

__global__ void add_k(const float* __restrict__ a, const float* __restrict__ b,
                      float* __restrict__ c, long n)
{
    long i = (long)blockIdx.x * blockDim.x + threadIdx.x;
    if (i < n) c[i] = a[i] + b[i];
}

__global__ void topk_k(const float* __restrict__ logits, int* __restrict__ topi,
                       float* __restrict__ coef)
{
    int t = (blockIdx.x * blockDim.x + threadIdx.x) >> 5;
    int lane = threadIdx.x & 31;
    if (t >= S_) return;
    const float* lr = logits + (long)t * E_;
    float v0 = lr[lane], v1 = lr[lane + 32];
    unsigned long long sel = 0ull;
    float tv[TOPK_]; int ti[TOPK_];
    #pragma unroll
    for (int k = 0; k < TOPK_; k++) {
        float c0 = ((sel >> lane) & 1ull) ? -1e30f : v0;
        float c1 = ((sel >> (lane + 32)) & 1ull) ? -1e30f : v1;
        float bv; int be;
        if (c0 >= c1) { bv = c0; be = lane; } else { bv = c1; be = lane + 32; }
        #pragma unroll
        for (int o = 16; o; o >>= 1) {
            float ov = __shfl_xor_sync(0xffffffffu, bv, o);
            int   oe = __shfl_xor_sync(0xffffffffu, be, o);
            if (ov > bv || (ov == bv && oe < be)) { bv = ov; be = oe; }
        }
        sel |= 1ull << be;
        tv[k] = bv; ti[k] = be;
    }
    if (lane == 0) {
        float mx = tv[0], ex[TOPK_], sum = 0.f;
        #pragma unroll
        for (int k = 0; k < TOPK_; k++) { ex[k] = expf(tv[k] - mx); sum += ex[k]; }
        float inv = 1.f / sum;
        #pragma unroll
        for (int k = 0; k < TOPK_; k++) { topi[t*TOPK_+k] = ti[k]; coef[t*TOPK_+k] = ex[k]*inv; }
    }
}

__global__ void assign_k(const int* __restrict__ topi, int* __restrict__ pos,
                         int* __restrict__ cnt)
{
    const int e = blockIdx.x;
    __shared__ int sw[8];
    __shared__ int stot;
    int lane = threadIdx.x & 31, wid = threadIdx.x >> 5;
    int base = 0;
    for (int chunk = 0; chunk < S_ * TOPK_; chunk += 256) {
        int i = chunk + threadIdx.x;
        int p = (topi[i] == e) ? 1 : 0;
        unsigned mask = __ballot_sync(0xffffffffu, p);
        int prefix = __popc(mask & ((1u << lane) - 1u));
        if (lane == 0) sw[wid] = __popc(mask);
        __syncthreads();
        if (threadIdx.x < 8) {
            int c = sw[threadIdx.x];
            int x = c;
            #pragma unroll
            for (int o = 1; o < 8; o <<= 1) {
                int y = __shfl_up_sync(0xffu, x, o);
                if ((int)threadIdx.x >= o) x += y;
            }
            sw[threadIdx.x] = x - c;
            if (threadIdx.x == 7) stot = x;
        }
        __syncthreads();
        if (p) pos[i] = base + sw[wid] + prefix;
        base += stot;
        __syncthreads();
    }
    if (threadIdx.x == 0) cnt[e] = (base < CAP_) ? base : CAP_;
}

__global__ void scatter_k(const __half* __restrict__ hxn2, const int* __restrict__ topi,
                          const int* __restrict__ pos, __half* __restrict__ buf)
{
    int i = blockIdx.x;
    int p = pos[i];
    if (p >= CAP_) return;
    int e = topi[i];
    int t = i >> 3;
    const uint2* src = reinterpret_cast<const uint2*>(hxn2 + (long)t * H_);
    uint2* dst = reinterpret_cast<uint2*>(buf + ((long)e * CAP_ + p) * H_);
    dst[threadIdx.x] = src[threadIdx.x];
}

__global__ void act_expert_k(const __half* __restrict__ ga, const __half* __restrict__ ua,
                             __half* __restrict__ o, const int* __restrict__ cnt)
{
    int e = blockIdx.x >> 8, c = blockIdx.x & 255;
    if (c >= cnt[e]) return;
    long base = ((long)e * CAP_ + c) * ID_;
    const __half2* g2 = reinterpret_cast<const __half2*>(ga + base);
    const __half2* u2 = reinterpret_cast<const __half2*>(ua + base);
    __half2* o2 = reinterpret_cast<__half2*>(o + base);
    for (int j = threadIdx.x; j < ID_ / 2; j += blockDim.x) {
        float2 g = __half22float2(g2[j]);
        float2 u = __half22float2(u2[j]);
        float a = (g.x / (1.f + expf(-g.x))) * u.x;
        float b = (g.y / (1.f + expf(-g.y))) * u.y;
        o2[j] = __floats2half2_rn(a, b);
    }
}

__global__ void act_fused_k(const __half* __restrict__ in, __half* __restrict__ o)
{
    long i = (long)blockIdx.x * blockDim.x + threadIdx.x;
    if (i >= (long)S_ * (ID_ / 2)) return;
    int row = (int)(i / (ID_ / 2)), col = (int)(i % (ID_ / 2));
    const __half2* g2 = reinterpret_cast<const __half2*>(in + (long)row * 2 * ID_) + col;
    const __half2* u2 = reinterpret_cast<const __half2*>(in + (long)row * 2 * ID_ + ID_) + col;
    float2 g = __half22float2(*g2);
    float2 u = __half22float2(*u2);
    float a = (g.x / (1.f + expf(-g.x))) * u.x;
    float b = (g.y / (1.f + expf(-g.y))) * u.y;
    reinterpret_cast<__half2*>(o + (long)row * ID_)[col] = __floats2half2_rn(a, b);
}

__global__ void final_k(const float* __restrict__ hres, const float* __restrict__ shb,
                        const __half* __restrict__ yy, const int* __restrict__ topi,
                        const int* __restrict__ pos, const float* __restrict__ coef,
                        float* __restrict__ out)
{
    int t = blockIdx.x, j = threadIdx.x;
    float4 a = reinterpret_cast<const float4*>(hres)[(long)t*256 + j];
    float4 b = reinterpret_cast<const float4*>(shb)[(long)t*256 + j];
    a.x += b.x; a.y += b.y; a.z += b.z; a.w += b.w;
    #pragma unroll
    for (int k = 0; k < TOPK_; k++) {
        int idx = t * TOPK_ + k;
        int p = pos[idx];
        if (p < CAP_) {
            float c = coef[idx];
            uint2 pk = reinterpret_cast<const uint2*>(yy + ((long)topi[idx]*CAP_ + p)*H_)[j];
            float2 f0 = __half22float2(*reinterpret_cast<__half2*>(&pk.x));
            float2 f1 = __half22float2(*reinterpret_cast<__half2*>(&pk.y));
            a.x += c*f0.x; a.y += c*f0.y; a.z += c*f1.x; a.w += c*f1.y;
        }
    }
    reinterpret_cast<float4*>(out)[(long)t*256 + j] = a;
}

// ---------- host-side smem size (R13 layout) ----------
static int smemB(int BN, int NST, bool bhalf) {
    int A_BY = 128 * 40 * 2;
    int B_BY = bhalf ? BN * 40 * 2 : 32 * (BN + 4) * 4;
    return NST * (A_BY + B_BY);
}

extern "C" void kernel_launch(void* const* d_in, const int* in_sizes, int n_in,
                              void* d_out, int out_size)
{
    (void)in_sizes; (void)n_in; (void)out_size;
    cudaStream_t st = 0;

    const int SM_W128 = smemB(128, 4, false);
    const int SM_W64  = smemB(64,  4, false);
    const int SM_SCR  = smemB(128, 2, true);
    const int SM_PV   = smemB(64,  4, true);
    cudaFuncSetAttribute(hgemm_k<128, 4, false, true >, cudaFuncAttributeMaxDynamicSharedMemorySize, SM_W128);
    cudaFuncSetAttribute(hgemm_k<64,  4, false, false>, cudaFuncAttributeMaxDynamicSharedMemorySize, SM_W64);
    cudaFuncSetAttribute(hgemm_k<64,  4, false, true >, cudaFuncAttributeMaxDynamicSharedMemorySize, SM_W64);
    cudaFuncSetAttribute(hgemm_k<128, 2, true,  true >, cudaFuncAttributeMaxDynamicSharedMemorySize, SM_SCR);
    cudaFuncSetAttribute(hgemm_k<64,  4, true,  true >, cudaFuncAttributeMaxDynamicSharedMemorySize, SM_PV);

    const float* x     = (const float*)d_in[0];
    const float* mask  = (const float*)d_in[1];
    const float* wln1  = (const float*)d_in[2];
    const float* wln2  = (const float*)d_in[3];
    const float* Wq    = (const float*)d_in[4];
    const float* Wk    = (const float*)d_in[5];
    const float* Wv    = (const float*)d_in[6];
    const float* Wo    = (const float*)d_in[7];
    const float* Wgate = (const float*)d_in[8];
    const float* Weg   = (const float*)d_in[9];
    const float* Weu   = (const float*)d_in[10];
    const float* Wed   = (const float*)d_in[11];
    const float* Wsg   = (const float*)d_in[12];
    const float* Wsu   = (const float*)d_in[13];
    const float* Wsd   = (const float*)d_in[14];
    float* out = (float*)d_out;

    void *p;
    #define GETF(sym, var) cudaGetSymbolAddress(&p, sym); float* var = (float*)p;
    #define GETH(sym, var) cudaGetSymbolAddress(&p, sym); __half* var = (__half*)p;
    #define GETI(sym, var) cudaGetSymbolAddress(&p, sym); int* var = (int*)p;
    GETF(g_xn1, xn1)  GETF(g_wqkv, wqkv) GETF(g_wsgsu, wsgsu)
    GETF(g_hres, hres) GETF(g_xn2, xn2)  GETF(g_logits, logits)
    GETF(g_coef, coef) GETF(g_shb, shb)
    GETH(h_xn1, hxn1) GETH(h_xn2, hxn2)  GETH(h_qkv, hqkv) GETH(h_qr, hqr)
    GETH(h_kr, hkr)   GETH(h_vt, hvt)    GETH(h_scraw, hscraw) GETH(h_sc, hsc)
    GETH(h_ao, hao)   GETH(h_buf, hbuf)  GETH(h_gga, hgga) GETH(h_uua, huua)
    GETH(h_gg, hgg)   GETH(h_yy, hyy)    GETH(h_sgsu, hsgsu) GETH(h_sg, hsg)
    GETI(g_topi, topi) GETI(g_pos, pos)  GETI(g_cnt, cnt)
    #undef GETF
    #undef GETH
    #undef GETI

    auto gw64 = [&](const __half* A, const float* B, float* C, int M, int N, int K,
                    int lda, int ldb, int ldc) {
        dim3 grid(N / 64, M / 128, 1);
        hgemm_k<64, 4, false, false><<<grid, 256, SM_W64, st>>>(
            A, B, C, K, lda, ldb, ldc, 0, 0, 0, 1, nullptr);
    };
    auto gw64h = [&](const __half* A, const float* B, __half* C, int M, int N, int K,
                     int lda, int ldb, int ldc) {
        dim3 grid(N / 64, M / 128, 1);
        hgemm_k<64, 4, false, true><<<grid, 256, SM_W64, st>>>(
            A, B, C, K, lda, ldb, ldc, 0, 0, 0, 1, nullptr);
    };
    auto gwh = [&](const __half* A, const float* B, __half* C, int M, int N, int K,
                   int lda, int ldb, int ldc, long sA, long sB, long sC, int batch,
                   const int* cc) {
        dim3 grid(N / 128, M / 128, batch);
        hgemm_k<128, 4, false, true><<<grid, 256, SM_W128, st>>>(
            A, B, C, K, lda, ldb, ldc, sA, sB, sC, 1, cc);
    };

    // ===== attention =====
    rmsnorm_k<<<S_, 256, 0, st>>>(x, wln1, nullptr, hxn1);                          // idx 0
    concat_qkv_w<<<(H_ * QKVN_ + 255)/256, 256, 0, st>>>(Wq, Wk, Wv, wqkv);         // idx 1
    concat_sgsu_w<<<(H_ * 2 * ID_ + 255)/256, 256, 0, st>>>(Wsg, Wsu, wsgsu);       // idx 2
    gw64h(hxn1, wqkv, hqkv, S_, QKVN_, H_, H_, QKVN_, QKVN_);                       // idx 3 (ncu)

    ropeall_k<<<(24*S_*HD_ + 255)/256, 256, 0, st>>>(hqkv, hqr, hkr, hvt);

    // scores: half output
    {
        dim3 grid(S_/128, S_/128, NH_);
        hgemm_k<128, 2, true, true><<<grid, 256, SM_SCR, st>>>(
            hqr, hkr, hscraw, HD_, HD_, HD_, S_,
            (long)S_*HD_, (long)S_*HD_, (long)S_*S_, REP_, nullptr);
    }

    softmax_k<<<dim3(S_, NH_), 256, 0, st>>>(hscraw, mask, hsc);

    {
        dim3 grid(1, S_/128, NH_);
        hgemm_k<64, 4, true, true><<<grid, 256, SM_PV, st>>>(
            hsc, hvt, hao, S_, S_, S_, H_,
            (long)S_*S_, (long)HD_*S_, 64L, REP_, nullptr);
    }

    gw64(hao, Wo, xn1, S_, H_, H_, H_, H_, H_);
    add_k<<<(S_*H_ + 255)/256, 256, 0, st>>>(x, xn1, hres, (long)S_*H_);

    // ===== MoE =====
    rmsnorm_k<<<S_, 256, 0, st>>>(hres, wln2, xn2, hxn2);

    sgemm64_k<<<dim3(1, S_/64), 256, 0, st>>>(xn2, Wgate, logits, S_, E_, H_);
    topk_k<<<(S_*32 + 255)/256, 256, 0, st>>>(logits, topi, coef);
    assign_k<<<E_, 256, 0, st>>>(topi, pos, cnt);

    scatter_k<<<S_*TOPK_, 256, 0, st>>>(hxn2, topi, pos, hbuf);

    gwh(hbuf, Weg, hgga, CAP_, ID_, H_, H_, ID_, ID_,
        (long)CAP_*H_, (long)H_*ID_, (long)CAP_*ID_, E_, cnt);
    gwh(hbuf, Weu, huua, CAP_, ID_, H_, H_, ID_, ID_,
        (long)CAP_*H_, (long)H_*ID_, (long)CAP_*ID_, E_, cnt);

    act_expert_k<<<E_ * CAP_, 256, 0, st>>>(hgga, huua, hgg, cnt);

    gwh(hgg, Wed, hyy, CAP_, H_, ID_, ID_, H_, H_,
        (long)CAP_*ID_, (long)ID_*H_, (long)CAP_*H_, E_, cnt);

    // shared expert
    gw64h(hxn2, wsgsu, hsgsu, S_, 2*ID_, H_, H_, 2*ID_, 2*ID_);
    act_fused_k<<<(int)(((long)S_*(ID_/2) + 255)/256), 256, 0, st>>>(hsgsu, hsg);
    gw64(hsg, Wsd, shb, S_, H_, ID_, ID_, H_, H_);

    final_k<<<S_, 256, 0, st>>>(hres, shb, hyy, topi, pos, coef, out);
}

// round 17
// speedup vs baseline: 1.1327x; 1.0843x over previous
#include <cuda_runtime.h>
#include <cuda_fp16.h>
#include <math.h>
#include <stdint.h>

#define S_    1024
#define H_    1024
#define NH_   16
#define KVH_  4
#define HD_   64
#define REP_  4
#define E_    64
#define TOPK_ 8
#define ID_   1408
#define CAP_  256
#define EPS_  1e-6f
#define QKVN_ (H_ + 2 * KVH_ * HD_)   // 1536

// fp32 scratch
__device__ float g_xn1 [S_ * H_];
__device__ float g_wqkv[H_ * QKVN_];
__device__ float g_wsgsu[H_ * 2 * ID_];
__device__ float g_hres[S_ * H_];
__device__ float g_xn2 [S_ * H_];
__device__ float g_logits[S_ * E_];
__device__ float g_coef[S_ * TOPK_];
__device__ float g_shb [S_ * H_];
__device__ int   g_topi[S_ * TOPK_];
__device__ int   g_pos [S_ * TOPK_];
__device__ int   g_cnt [E_];
// fp16 activation scratch
__device__ __half h_xn1[S_ * H_];
__device__ __half h_xn2[S_ * H_];
__device__ __half h_qkv[S_ * QKVN_];
__device__ __half h_qr [NH_ * S_ * HD_];
__device__ __half h_kr [KVH_ * S_ * HD_];
__device__ __half h_vt [KVH_ * HD_ * S_];
__device__ __half h_scraw[(long)NH_ * S_ * S_];
__device__ __half h_sc [(long)NH_ * S_ * S_];
__device__ __half h_ao [S_ * H_];
__device__ __half h_buf[(long)E_ * CAP_ * H_];
__device__ __half h_gga[(long)E_ * CAP_ * ID_];
__device__ __half h_uua[(long)E_ * CAP_ * ID_];
__device__ __half h_gg [(long)E_ * CAP_ * ID_];
__device__ __half h_yy [(long)E_ * CAP_ * H_];
__device__ __half h_sgsu[S_ * 2 * ID_];
__device__ __half h_sg [S_ * ID_];

// ---------- helpers ----------
__device__ __forceinline__ uint32_t smem_u32(const void* p) {
    uint32_t a;
    asm("{ .reg .u64 t; cvta.to.shared.u64 t, %1; cvt.u32.u64 %0, t; }" : "=r"(a) : "l"(p));
    return a;
}
__device__ __forceinline__ uint32_t cvt2h(float lo, float hi) {
    __half2 h = __floats2half2_rn(lo, hi);
    return *reinterpret_cast<uint32_t*>(&h);
}
__device__ __forceinline__ void cp16(uint32_t dst, const void* src) {
    asm volatile("cp.async.cg.shared.global [%0], [%1], 16;" :: "r"(dst), "l"(src));
}
__device__ __forceinline__ void cp_commit() { asm volatile("cp.async.commit_group;" ::: "memory"); }
__device__ __forceinline__ void cp_wait(int n) {
    if (n <= 0)      asm volatile("cp.async.wait_group 0;" ::: "memory");
    else if (n == 1) asm volatile("cp.async.wait_group 1;" ::: "memory");
    else if (n == 2) asm volatile("cp.async.wait_group 2;" ::: "memory");
    else             asm volatile("cp.async.wait_group 3;" ::: "memory");
}
__device__ __forceinline__ void ldm_x4(uint32_t* r, uint32_t a) {
    asm volatile("ldmatrix.sync.aligned.m8n8.x4.shared.b16 {%0,%1,%2,%3}, [%4];"
        : "=r"(r[0]), "=r"(r[1]), "=r"(r[2]), "=r"(r[3]) : "r"(a));
}
__device__ __forceinline__ void mma16816(float* d, const uint32_t* a, const uint32_t* b) {
    asm volatile("mma.sync.aligned.m16n8k16.row.col.f32.f16.f16.f32 "
        "{%0,%1,%2,%3}, {%4,%5,%6,%7}, {%8,%9}, {%0,%1,%2,%3};"
        : "+f"(d[0]), "+f"(d[1]), "+f"(d[2]), "+f"(d[3])
        : "r"(a[0]), "r"(a[1]), "r"(a[2]), "r"(a[3]), "r"(b[0]), "r"(b[1]));
}

// ---------- fp16 GEMM (proven mainloop; unchanged) ----------
template<int BN, int NST, bool BHALF, bool CHALF>
__global__ void __launch_bounds__(256, 2) hgemm_k(
    const __half* __restrict__ A, const void* __restrict__ Bv, void* __restrict__ Cv,
    int K, int lda, int ldb, int ldc, long sA, long sB, long sC, int bDiv,
    const int* __restrict__ cnt)
{
    constexpr int BM = 128, BK = 32;
    constexpr int LDA  = 40;
    constexpr int LDBF = BN + 4;
    constexpr int A_BY = BM * LDA * 2;
    constexpr int B_BY = BHALF ? BN * 40 * 2 : BK * LDBF * 4;
    constexpr int STG_BY = A_BY + B_BY;
    constexpr int WGN = BN / 32, WGM = 8 / WGN;
    constexpr int WM  = BM / WGM, MT = WM / 16, NT = 4;

    const int row0 = blockIdx.y * BM;
    if (cnt != nullptr && row0 >= cnt[blockIdx.z]) return;

    extern __shared__ char sm[];
    const uint32_t smb = smem_u32(sm);
    const int tid = threadIdx.x, wid = tid >> 5, lane = tid & 31;
    const int qrw = lane >> 2, qc = lane & 3;
    A += (long)blockIdx.z * sA;
    const __half* Bh = BHALF ? (const __half*)Bv + (long)(blockIdx.z / bDiv) * sB : nullptr;
    const float*  Bf = BHALF ? nullptr : (const float*)Bv + (long)(blockIdx.z / bDiv) * sB;
    const int col0 = blockIdx.x * BN;
    const int wm0 = (wid / WGN) * WM;
    const int wn0 = (wid % WGN) * 32;
    const int nch = K / BK;
    const uint32_t aoff = ((wm0 + (lane & 15)) * LDA + ((lane >> 4) << 3)) * 2;
    const uint32_t boff = ((wn0 + ((lane >> 4) << 3) + (lane & 7)) * 40
                           + (((lane >> 3) & 1) << 3)) * 2;

    auto fill = [&](int c) {
        char* Ss = sm + (c % NST) * STG_BY;
        __half* As = (__half*)Ss;
        const int k0 = c * BK;
        const __half* Ag = A + (long)row0 * lda + k0;
        #pragma unroll
        for (int i = 0; i < 2; i++) {
            int idx = i * 256 + tid;
            int r = idx >> 2, sg = idx & 3;
            cp16(smem_u32(As + r * LDA + sg * 8), Ag + (long)r * lda + sg * 8);
        }
        if (BHALF) {
            __half* Bs = (__half*)(Ss + A_BY);
            const __half* Bg = Bh + (long)col0 * ldb + k0;
            #pragma unroll
            for (int i = 0; i < BN / 64; i++) {
                int idx = i * 256 + tid;
                int r = idx >> 2, sg = idx & 3;
                cp16(smem_u32(Bs + r * 40 + sg * 8), Bg + (long)r * ldb + sg * 8);
            }
        } else {
            float* Bs = (float*)(Ss + A_BY);
            const float* Bg = Bf + (long)k0 * ldb + col0;
            #pragma unroll
            for (int i = 0; i < BN / 32; i++) {
                int idx = i * 256 + tid;
                int r = idx / (BN / 4), sg = idx % (BN / 4);
                cp16(smem_u32(Bs + r * LDBF + sg * 4), Bg + (long)r * ldb + sg * 4);
            }
        }
        cp_commit();
    };

    float acc[MT][NT][4];
    #pragma unroll
    for (int m = 0; m < MT; m++)
        #pragma unroll
        for (int n = 0; n < NT; n++)
            #pragma unroll
            for (int j = 0; j < 4; j++) acc[m][n][j] = 0.f;

    const int PF = NST - 1;
    const int F0 = (nch < PF) ? nch : PF;
    for (int c = 0; c < F0; c++) fill(c);
    int g = F0;

    for (int c = 0; c < nch; c++) {
        cp_wait(g - (c + 1));
        __syncthreads();
        if (c + PF < nch) { fill(c + PF); g++; }

        const uint32_t As_u = smb + (c % NST) * STG_BY;
        const uint32_t Bs_u = As_u + A_BY;
        #pragma unroll
        for (int ks = 0; ks < 2; ks++) {
            const int kk = ks * 16;
            uint32_t af[MT][4], bf[NT][2];
            #pragma unroll
            for (int mt = 0; mt < MT; mt++)
                ldm_x4(af[mt], As_u + aoff + (mt * 16 * LDA + kk) * 2);
            if (BHALF) {
                uint32_t t0[4], t1[4];
                ldm_x4(t0, Bs_u + boff + kk * 2);
                ldm_x4(t1, Bs_u + boff + (16 * 40 + kk) * 2);
                bf[0][0] = t0[0]; bf[0][1] = t0[1];
                bf[1][0] = t0[2]; bf[1][1] = t0[3];
                bf[2][0] = t1[0]; bf[2][1] = t1[1];
                bf[3][0] = t1[2]; bf[3][1] = t1[3];
            } else {
                const float* Bsf = (const float*)(sm + (c % NST) * STG_BY + A_BY);
                #pragma unroll
                for (int nt = 0; nt < NT; nt++) {
                    const float* bp = Bsf + (kk + 2 * qc) * LDBF + wn0 + nt * 8 + qrw;
                    bf[nt][0] = cvt2h(bp[0], bp[LDBF]);
                    bf[nt][1] = cvt2h(bp[8 * LDBF], bp[9 * LDBF]);
                }
            }
            #pragma unroll
            for (int mt = 0; mt < MT; mt++)
                #pragma unroll
                for (int nt = 0; nt < NT; nt++)
                    mma16816(acc[mt][nt], af[mt], bf[nt]);
        }
    }

    if (CHALF) {
        __half* Ch = (__half*)Cv + (long)blockIdx.z * sC;
        #pragma unroll
        for (int mt = 0; mt < MT; mt++) {
            const int r = row0 + wm0 + mt * 16 + qrw;
            #pragma unroll
            for (int nt = 0; nt < NT; nt++) {
                const int cc = col0 + wn0 + nt * 8 + qc * 2;
                *reinterpret_cast<uint32_t*>(Ch + (long)r * ldc + cc)
                    = cvt2h(acc[mt][nt][0], acc[mt][nt][1]);
                *reinterpret_cast<uint32_t*>(Ch + (long)(r + 8) * ldc + cc)
                    = cvt2h(acc[mt][nt][2], acc[mt][nt][3]);
            }
        }
    } else {
        float* Cf = (float*)Cv + (long)blockIdx.z * sC;
        #pragma unroll
        for (int mt = 0; mt < MT; mt++) {
            const int r = row0 + wm0 + mt * 16 + qrw;
            #pragma unroll
            for (int nt = 0; nt < NT; nt++) {
                const int cc = col0 + wn0 + nt * 8 + qc * 2;
                *reinterpret_cast<float2*>(Cf + (long)r * ldc + cc) =
                    make_float2(acc[mt][nt][0], acc[mt][nt][1]);
                *reinterpret_cast<float2*>(Cf + (long)(r + 8) * ldc + cc) =
                    make_float2(acc[mt][nt][2], acc[mt][nt][3]);
            }
        }
    }
}

// ---------- exact fp32 gemm for gate logits ----------
__global__ void sgemm64_k(const float* __restrict__ A, const float* __restrict__ B,
                          float* __restrict__ C, int M, int N, int K)
{
    const int tid = threadIdx.x;
    const int row0 = blockIdx.y * 64, col0 = blockIdx.x * 64;
    __shared__ float As[16][68];
    __shared__ float Bs[16][68];
    float acc[4][4] = {};
    const int tRow = (tid / 16) * 4, tCol = (tid % 16) * 4;
    const int aRow = tid / 4, aK = (tid % 4) * 4;
    const int bR = tid / 16, bC = (tid % 16) * 4;
    for (int k0 = 0; k0 < K; k0 += 16) {
        {
            int gr = row0 + aRow, gk = k0 + aK;
            float4 v = make_float4(0,0,0,0);
            if (gr < M && gk + 3 < K) v = *reinterpret_cast<const float4*>(A + (long)gr*K + gk);
            As[aK+0][aRow]=v.x; As[aK+1][aRow]=v.y; As[aK+2][aRow]=v.z; As[aK+3][aRow]=v.w;
        }
        {
            int gk = k0 + bR, gn = col0 + bC;
            float4 v = make_float4(0,0,0,0);
            if (gk < K && gn + 3 < N) v = *reinterpret_cast<const float4*>(B + (long)gk*N + gn);
            *reinterpret_cast<float4*>(&Bs[bR][bC]) = v;
        }
        __syncthreads();
        #pragma unroll
        for (int k = 0; k < 16; k++) {
            float rA[4], rB[4];
            #pragma unroll
            for (int m = 0; m < 4; m++) rA[m] = As[k][tRow+m];
            #pragma unroll
            for (int n = 0; n < 4; n++) rB[n] = Bs[k][tCol+n];
            #pragma unroll
            for (int m = 0; m < 4; m++)
                #pragma unroll
                for (int n = 0; n < 4; n++) acc[m][n] += rA[m]*rB[n];
        }
        __syncthreads();
    }
    #pragma unroll
    for (int m = 0; m < 4; m++) {
        int gr = row0 + tRow + m;
        if (gr >= M) continue;
        #pragma unroll
        for (int n = 0; n < 4; n++) {
            int gc = col0 + tCol + n;
            if (gc < N) C[(long)gr*N + gc] = acc[m][n];
        }
    }
}

// ---------- reductions ----------
__device__ __forceinline__ float warpSum(float v) {
    #pragma unroll
    for (int o = 16; o; o >>= 1) v += __shfl_xor_sync(0xffffffffu, v, o);
    return v;
}
__device__ __forceinline__ float warpMax(float v) {
    #pragma unroll
    for (int o = 16; o; o >>= 1) v = fmaxf(v, __shfl_xor_sync(0xffffffffu, v, o));
    return v;
}
__device__ float blockSum(float v) {
    __shared__ float sh[32]; __shared__ float tot;
    int lane = threadIdx.x & 31, wid = threadIdx.x >> 5;
    v = warpSum(v);
    if (lane == 0) sh[wid] = v;
    __syncthreads();
    int nw = (blockDim.x + 31) >> 5;
    float w = (threadIdx.x < nw) ? sh[threadIdx.x] : 0.f;
    if (wid == 0) { w = warpSum(w); if (lane == 0) tot = w; }
    __syncthreads();
    float r = tot; __syncthreads(); return r;
}
__device__ float blockMax(float v) {
    __shared__ float sh[32]; __shared__ float tot;
    int lane = threadIdx.x & 31, wid = threadIdx.x >> 5;
    v = warpMax(v);
    if (lane == 0) sh[wid] = v;
    __syncthreads();
    int nw = (blockDim.x + 31) >> 5;
    float w = (threadIdx.x < nw) ? sh[threadIdx.x] : -1e30f;
    if (wid == 0) { w = warpMax(w); if (lane == 0) tot = w; }
    __syncthreads();
    float r = tot; __syncthreads(); return r;
}

// ---------- small kernels ----------
__global__ void concat_qkv_w(const float* __restrict__ Wq, const float* __restrict__ Wk,
                             const float* __restrict__ Wv, float* __restrict__ W)
{
    int idx = blockIdx.x * blockDim.x + threadIdx.x;
    if (idx >= H_ * QKVN_) return;
    int r = idx / QKVN_, c = idx % QKVN_;
    float v;
    if (c < H_)                 v = Wq[(long)r * H_ + c];
    else if (c < H_ + KVH_*HD_) v = Wk[(long)r * (KVH_*HD_) + (c - H_)];
    else                        v = Wv[(long)r * (KVH_*HD_) + (c - H_ - KVH_*HD_)];
    W[idx] = v;
}

__global__ void concat_sgsu_w(const float* __restrict__ Wsg, const float* __restrict__ Wsu,
                              float* __restrict__ W)
{
    int idx = blockIdx.x * blockDim.x + threadIdx.x;
    if (idx >= H_ * 2 * ID_) return;
    int r = idx / (2 * ID_), c = idx % (2 * ID_);
    W[idx] = (c < ID_) ? Wsg[(long)r * ID_ + c] : Wsu[(long)r * ID_ + (c - ID_)];
}

__global__ void rmsnorm_k(const float* __restrict__ x, const float* __restrict__ w,
                          float* __restrict__ y, __half* __restrict__ yh)
{
    int t = blockIdx.x;
    const float* xr = x + (long)t * H_;
    float s = 0.f;
    for (int i = threadIdx.x; i < H_; i += blockDim.x) { float v = xr[i]; s += v * v; }
    s = blockSum(s);
    float inv = rsqrtf(s / (float)H_ + EPS_);
    for (int i = threadIdx.x; i < H_; i += blockDim.x) {
        float v = xr[i] * inv * w[i];
        if (y)  y[(long)t * H_ + i] = v;
        yh[(long)t * H_ + i] = __float2half_rn(v);
    }
}

__global__ void ropeall_k(const __half* __restrict__ qkv, __half* __restrict__ hqr,
                          __half* __restrict__ hkr, __half* __restrict__ hvt)
{
    int idx = blockIdx.x * blockDim.x + threadIdx.x;
    if (idx >= 24 * S_ * HD_) return;
    int g = idx / (S_ * HD_);
    int rem = idx - g * (S_ * HD_);
    if (g < 20) {
        int d = rem % HD_, s = rem / HD_;
        int h, off; __half* dst;
        if (g < 16) { h = g;      off = 0;  dst = hqr; }
        else        { h = g - 16; off = H_; dst = hkr; }
        const __half* p = qkv + (long)s * QKVN_ + off + h * HD_;
        float v  = __half2float(p[d]);
        float pr = (d < 32) ? -__half2float(p[d + 32]) : __half2float(p[d - 32]);
        int i = d & 31;
        float inv = expf(-(float)i * (9.210340371976184f / 32.f));
        float ang = (float)s * inv, sn, cs;
        sincosf(ang, &sn, &cs);
        dst[((long)h * S_ + s) * HD_ + d] = __float2half_rn(v * cs + pr * sn);
    } else {
        int h = g - 20;
        int s = rem % S_, d = rem / S_;
        hvt[((long)h * HD_ + d) * S_ + s] =
            qkv[(long)s * QKVN_ + H_ + KVH_*HD_ + h * HD_ + d];
    }
}

__global__ void softmax_k(const __half* __restrict__ sc, const float* __restrict__ mask,
                          __half* __restrict__ pr)
{
    int r = blockIdx.x, h = blockIdx.y;
    const uint2* row = reinterpret_cast<const uint2*>(sc + ((long)h * S_ + r) * S_);
    const float4* mr = reinterpret_cast<const float4*>(mask + (long)r * S_);
    int j = threadIdx.x;
    uint2 pk = row[j];
    float2 s0 = __half22float2(*reinterpret_cast<__half2*>(&pk.x));
    float2 s1 = __half22float2(*reinterpret_cast<__half2*>(&pk.y));
    float4 m = mr[j];
    float4 v;
    v.x = s0.x * 0.125f + m.x;
    v.y = s0.y * 0.125f + m.y;
    v.z = s1.x * 0.125f + m.z;
    v.w = s1.y * 0.125f + m.w;
    float mx = fmaxf(fmaxf(v.x, v.y), fmaxf(v.z, v.w));
    mx = blockMax(mx);
    v.x = expf(v.x - mx); v.y = expf(v.y - mx);
    v.z = expf(v.z - mx); v.w = expf(v.w - mx);
    float sum = v.x + v.y + v.z + v.w;
    sum = blockSum(sum);
    float inv = 1.f / sum;
    uint2 po = make_uint2(cvt2h(v.x * inv, v.y * inv), cvt2h(v.z * inv, v.w * inv));
    reinterpret_cast<uint2*>(pr + ((long)h * S_ + r) * S_)[j] = po;
}

__global__ void add_k(const float* __restrict__ a, const float* __restrict__ b,
                      float* __restrict__ c, long n)
{
    long i = (long)blockIdx.x * blockDim.x + threadIdx.x;
    if (i < n) c[i] = a[i] + b[i];
}

__global__ void topk_k(const float* __restrict__ logits, int* __restrict__ topi,
                       float* __restrict__ coef)
{
    int t = (blockIdx.x * blockDim.x + threadIdx.x) >> 5;
    int lane = threadIdx.x & 31;
    if (t >= S_) return;
    const float* lr = logits + (long)t * E_;
    float v0 = lr[lane], v1 = lr[lane + 32];
    unsigned long long sel = 0ull;
    float tv[TOPK_]; int ti[TOPK_];
    #pragma unroll
    for (int k = 0; k < TOPK_; k++) {
        float c0 = ((sel >> lane) & 1ull) ? -1e30f : v0;
        float c1 = ((sel >> (lane + 32)) & 1ull) ? -1e30f : v1;
        float bv; int be;
        if (c0 >= c1) { bv = c0; be = lane; } else { bv = c1; be = lane + 32; }
        #pragma unroll
        for (int o = 16; o; o >>= 1) {
            float ov = __shfl_xor_sync(0xffffffffu, bv, o);
            int   oe = __shfl_xor_sync(0xffffffffu, be, o);
            if (ov > bv || (ov == bv && oe < be)) { bv = ov; be = oe; }
        }
        sel |= 1ull << be;
        tv[k] = bv; ti[k] = be;
    }
    if (lane == 0) {
        float mx = tv[0], ex[TOPK_], sum = 0.f;
        #pragma unroll
        for (int k = 0; k < TOPK_; k++) { ex[k] = expf(tv[k] - mx); sum += ex[k]; }
        float inv = 1.f / sum;
        #pragma unroll
        for (int k = 0; k < TOPK_; k++) { topi[t*TOPK_+k] = ti[k]; coef[t*TOPK_+k] = ex[k]*inv; }
    }
}

__global__ void assign_k(const int* __restrict__ topi, int* __restrict__ pos,
                         int* __restrict__ cnt)
{
    const int e = blockIdx.x;
    __shared__ int sw[8];
    __shared__ int stot;
    int lane = threadIdx.x & 31, wid = threadIdx.x >> 5;
    int base = 0;
    for (int chunk = 0; chunk < S_ * TOPK_; chunk += 256) {
        int i = chunk + threadIdx.x;
        int p = (topi[i] == e) ? 1 : 0;
        unsigned mask = __ballot_sync(0xffffffffu, p);
        int prefix = __popc(mask & ((1u << lane) - 1u));
        if (lane == 0) sw[wid] = __popc(mask);
        __syncthreads();
        if (threadIdx.x < 8) {
            int c = sw[threadIdx.x];
            int x = c;
            #pragma unroll
            for (int o = 1; o < 8; o <<= 1) {
                int y = __shfl_up_sync(0xffu, x, o);
                if ((int)threadIdx.x >= o) x += y;
            }
            sw[threadIdx.x] = x - c;
            if (threadIdx.x == 7) stot = x;
        }
        __syncthreads();
        if (p) pos[i] = base + sw[wid] + prefix;
        base += stot;
        __syncthreads();
    }
    if (threadIdx.x == 0) cnt[e] = (base < CAP_) ? base : CAP_;
}

__global__ void scatter_k(const __half* __restrict__ hxn2, const int* __restrict__ topi,
                          const int* __restrict__ pos, __half* __restrict__ buf)
{
    int i = blockIdx.x;
    int p = pos[i];
    if (p >= CAP_) return;
    int e = topi[i];
    int t = i >> 3;
    const uint2* src = reinterpret_cast<const uint2*>(hxn2 + (long)t * H_);
    uint2* dst = reinterpret_cast<uint2*>(buf + ((long)e * CAP_ + p) * H_);
    dst[threadIdx.x] = src[threadIdx.x];
}

__global__ void act_expert_k(const __half* __restrict__ ga, const __half* __restrict__ ua,
                             __half* __restrict__ o, const int* __restrict__ cnt)
{
    int e = blockIdx.x >> 8, c = blockIdx.x & 255;
    if (c >= cnt[e]) return;
    long base = ((long)e * CAP_ + c) * ID_;
    const __half2* g2 = reinterpret_cast<const __half2*>(ga + base);
    const __half2* u2 = reinterpret_cast<const __half2*>(ua + base);
    __half2* o2 = reinterpret_cast<__half2*>(o + base);
    for (int j = threadIdx.x; j < ID_ / 2; j += blockDim.x) {
        float2 g = __half22float2(g2[j]);
        float2 u = __half22float2(u2[j]);
        float a = (g.x / (1.f + expf(-g.x))) * u.x;
        float b = (g.y / (1.f + expf(-g.y))) * u.y;
        o2[j] = __floats2half2_rn(a, b);
    }
}

__global__ void act_fused_k(const __half* __restrict__ in, __half* __restrict__ o)
{
    long i = (long)blockIdx.x * blockDim.x + threadIdx.x;
    if (i >= (long)S_ * (ID_ / 2)) return;
    int row = (int)(i / (ID_ / 2)), col = (int)(i % (ID_ / 2));
    const __half2* g2 = reinterpret_cast<const __half2*>(in + (long)row * 2 * ID_) + col;
    const __half2* u2 = reinterpret_cast<const __half2*>(in + (long)row * 2 * ID_ + ID_) + col;
    float2 g = __half22float2(*g2);
    float2 u = __half22float2(*u2);
    float a = (g.x / (1.f + expf(-g.x))) * u.x;
    float b = (g.y / (1.f + expf(-g.y))) * u.y;
    reinterpret_cast<__half2*>(o + (long)row * ID_)[col] = __floats2half2_rn(a, b);
}

__global__ void final_k(const float* __restrict__ hres, const float* __restrict__ shb,
                        const __half* __restrict__ yy, const int* __restrict__ topi,
                        const int* __restrict__ pos, const float* __restrict__ coef,
                        float* __restrict__ out)
{
    int t = blockIdx.x, j = threadIdx.x;
    float4 a = reinterpret_cast<const float4*>(hres)[(long)t*256 + j];
    float4 b = reinterpret_cast<const float4*>(shb)[(long)t*256 + j];
    a.x += b.x; a.y += b.y; a.z += b.z; a.w += b.w;
    #pragma unroll
    for (int k = 0; k < TOPK_; k++) {
        int idx = t * TOPK_ + k;
        int p = pos[idx];
        if (p < CAP_) {
            float c = coef[idx];
            uint2 pk = reinterpret_cast<const uint2*>(yy + ((long)topi[idx]*CAP_ + p)*H_)[j];
            float2 f0 = __half22float2(*reinterpret_cast<__half2*>(&pk.x));
            float2 f1 = __half22float2(*reinterpret_cast<__half2*>(&pk.y));
            a.x += c*f0.x; a.y += c*f0.y; a.z += c*f1.x; a.w += c*f1.y;
        }
    }
    reinterpret_cast<float4*>(out)[(long)t*256 + j] = a;
}

// ---------- host-side smem size ----------
static int smemB(int BN, int NST, bool bhalf) {
    int A_BY = 128 * 40 * 2;
    int B_BY = bhalf ? BN * 40 * 2 : 32 * (BN + 4) * 4;
    return NST * (A_BY + B_BY);
}

extern "C" void kernel_launch(void* const* d_in, const int* in_sizes, int n_in,
                              void* d_out, int out_size)
{
    (void)in_sizes; (void)n_in; (void)out_size;
    cudaStream_t st = 0;

    // side stream for shared-expert overlap (created per call; kernel_launch
    // is invoked only for correctness + capture, so no unbounded growth)
    cudaStream_t s2;
    cudaStreamCreateWithFlags(&s2, cudaStreamNonBlocking);
    cudaEvent_t ev0, ev1, ev2;
    cudaEventCreateWithFlags(&ev0, cudaEventDisableTiming);
    cudaEventCreateWithFlags(&ev1, cudaEventDisableTiming);
    cudaEventCreateWithFlags(&ev2, cudaEventDisableTiming);

    const int SM_W128 = smemB(128, 4, false);
    const int SM_W64  = smemB(64,  4, false);
    const int SM_SCR  = smemB(128, 2, true);
    const int SM_PV   = smemB(64,  4, true);
    cudaFuncSetAttribute(hgemm_k<128, 4, false, true >, cudaFuncAttributeMaxDynamicSharedMemorySize, SM_W128);
    cudaFuncSetAttribute(hgemm_k<64,  4, false, false>, cudaFuncAttributeMaxDynamicSharedMemorySize, SM_W64);
    cudaFuncSetAttribute(hgemm_k<64,  4, false, true >, cudaFuncAttributeMaxDynamicSharedMemorySize, SM_W64);
    cudaFuncSetAttribute(hgemm_k<128, 2, true,  true >, cudaFuncAttributeMaxDynamicSharedMemorySize, SM_SCR);
    cudaFuncSetAttribute(hgemm_k<64,  4, true,  true >, cudaFuncAttributeMaxDynamicSharedMemorySize, SM_PV);

    const float* x     = (const float*)d_in[0];
    const float* mask  = (const float*)d_in[1];
    const float* wln1  = (const float*)d_in[2];
    const float* wln2  = (const float*)d_in[3];
    const float* Wq    = (const float*)d_in[4];
    const float* Wk    = (const float*)d_in[5];
    const float* Wv    = (const float*)d_in[6];
    const float* Wo    = (const float*)d_in[7];
    const float* Wgate = (const float*)d_in[8];
    const float* Weg   = (const float*)d_in[9];
    const float* Weu   = (const float*)d_in[10];
    const float* Wed   = (const float*)d_in[11];
    const float* Wsg   = (const float*)d_in[12];
    const float* Wsu   = (const float*)d_in[13];
    const float* Wsd   = (const float*)d_in[14];
    float* out = (float*)d_out;

    void *p;
    #define GETF(sym, var) cudaGetSymbolAddress(&p, sym); float* var = (float*)p;
    #define GETH(sym, var) cudaGetSymbolAddress(&p, sym); __half* var = (__half*)p;
    #define GETI(sym, var) cudaGetSymbolAddress(&p, sym); int* var = (int*)p;
    GETF(g_xn1, xn1)  GETF(g_wqkv, wqkv) GETF(g_wsgsu, wsgsu)
    GETF(g_hres, hres) GETF(g_xn2, xn2)  GETF(g_logits, logits)
    GETF(g_coef, coef) GETF(g_shb, shb)
    GETH(h_xn1, hxn1) GETH(h_xn2, hxn2)  GETH(h_qkv, hqkv) GETH(h_qr, hqr)
    GETH(h_kr, hkr)   GETH(h_vt, hvt)    GETH(h_scraw, hscraw) GETH(h_sc, hsc)
    GETH(h_ao, hao)   GETH(h_buf, hbuf)  GETH(h_gga, hgga) GETH(h_uua, huua)
    GETH(h_gg, hgg)   GETH(h_yy, hyy)    GETH(h_sgsu, hsgsu) GETH(h_sg, hsg)
    GETI(g_topi, topi) GETI(g_pos, pos)  GETI(g_cnt, cnt)
    #undef GETF
    #undef GETH
    #undef GETI

    auto gw64 = [&](const __half* A, const float* B, float* C, int M, int N, int K,
                    int lda, int ldb, int ldc, cudaStream_t ss) {
        dim3 grid(N / 64, M / 128, 1);
        hgemm_k<64, 4, false, false><<<grid, 256, SM_W64, ss>>>(
            A, B, C, K, lda, ldb, ldc, 0, 0, 0, 1, nullptr);
    };
    auto gw64h = [&](const __half* A, const float* B, __half* C, int M, int N, int K,
                     int lda, int ldb, int ldc, cudaStream_t ss) {
        dim3 grid(N / 64, M / 128, 1);
        hgemm_k<64, 4, false, true><<<grid, 256, SM_W64, ss>>>(
            A, B, C, K, lda, ldb, ldc, 0, 0, 0, 1, nullptr);
    };
    auto gwh = [&](const __half* A, const float* B, __half* C, int M, int N, int K,
                   int lda, int ldb, int ldc, long sA, long sB, long sC, int batch,
                   const int* cc) {
        dim3 grid(N / 128, M / 128, batch);
        hgemm_k<128, 4, false, true><<<grid, 256, SM_W128, st>>>(
            A, B, C, K, lda, ldb, ldc, sA, sB, sC, 1, cc);
    };

    // fork s2: shared-expert weight concat overlaps attention
    cudaEventRecord(ev0, st);
    cudaStreamWaitEvent(s2, ev0, 0);
    concat_sgsu_w<<<(H_ * 2 * ID_ + 255)/256, 256, 0, s2>>>(Wsg, Wsu, wsgsu);

    // ===== attention (main stream) =====
    rmsnorm_k<<<S_, 256, 0, st>>>(x, wln1, nullptr, hxn1);
    concat_qkv_w<<<(H_ * QKVN_ + 255)/256, 256, 0, st>>>(Wq, Wk, Wv, wqkv);
    gw64h(hxn1, wqkv, hqkv, S_, QKVN_, H_, H_, QKVN_, QKVN_, st);

    ropeall_k<<<(24*S_*HD_ + 255)/256, 256, 0, st>>>(hqkv, hqr, hkr, hvt);

    {
        dim3 grid(S_/128, S_/128, NH_);
        hgemm_k<128, 2, true, true><<<grid, 256, SM_SCR, st>>>(
            hqr, hkr, hscraw, HD_, HD_, HD_, S_,
            (long)S_*HD_, (long)S_*HD_, (long)S_*S_, REP_, nullptr);
    }

    softmax_k<<<dim3(S_, NH_), 256, 0, st>>>(hscraw, mask, hsc);

    {
        dim3 grid(1, S_/128, NH_);
        hgemm_k<64, 4, true, true><<<grid, 256, SM_PV, st>>>(
            hsc, hvt, hao, S_, S_, S_, H_,
            (long)S_*S_, (long)HD_*S_, 64L, REP_, nullptr);
    }

    gw64(hao, Wo, xn1, S_, H_, H_, H_, H_, H_, st);
    add_k<<<(S_*H_ + 255)/256, 256, 0, st>>>(x, xn1, hres, (long)S_*H_);

    // ===== MoE =====
    rmsnorm_k<<<S_, 256, 0, st>>>(hres, wln2, xn2, hxn2);

    // fork: shared-expert chain on s2 (needs hxn2 + wsgsu)
    cudaEventRecord(ev1, st);
    cudaStreamWaitEvent(s2, ev1, 0);
    gw64h(hxn2, wsgsu, hsgsu, S_, 2*ID_, H_, H_, 2*ID_, 2*ID_, s2);
    act_fused_k<<<(int)(((long)S_*(ID_/2) + 255)/256), 256, 0, s2>>>(hsgsu, hsg);
    gw64(hsg, Wsd, shb, S_, H_, ID_, ID_, H_, H_, s2);
    cudaEventRecord(ev2, s2);

    // expert chain on main stream
    sgemm64_k<<<dim3(1, S_/64), 256, 0, st>>>(xn2, Wgate, logits, S_, E_, H_);
    topk_k<<<(S_*32 + 255)/256, 256, 0, st>>>(logits, topi, coef);
    assign_k<<<E_, 256, 0, st>>>(topi, pos, cnt);

    scatter_k<<<S_*TOPK_, 256, 0, st>>>(hxn2, topi, pos, hbuf);

    gwh(hbuf, Weg, hgga, CAP_, ID_, H_, H_, ID_, ID_,
        (long)CAP_*H_, (long)H_*ID_, (long)CAP_*ID_, E_, cnt);
    gwh(hbuf, Weu, huua, CAP_, ID_, H_, H_, ID_, ID_,
        (long)CAP_*H_, (long)H_*ID_, (long)CAP_*ID_, E_, cnt);

    act_expert_k<<<E_ * CAP_, 256, 0, st>>>(hgga, huua, hgg, cnt);

    gwh(hgg, Wed, hyy, CAP_, H_, ID_, ID_, H_, H_,
        (long)CAP_*ID_, (long)ID_*H_, (long)CAP_*H_, E_, cnt);

    // join shared-expert chain, then final
    cudaStreamWaitEvent(st, ev2, 0);
    final_k<<<S_, 256, 0, st>>>(hres, shb, hyy, topi, pos, coef, out);
}